// round 3
// baseline (speedup 1.0000x reference)
#include <cuda_runtime.h>
#include <cstdint>

#define NT 512
constexpr int Tn  = 16;
constexpr int Bn  = 16;
constexpr int Nn  = 1024;
constexpr int En  = 16384;
constexpr int Fin = 128;
constexpr int Hn  = 256;
constexpr int Kn  = 820;
constexpr int NG  = Tn * Bn;   // 256 graphs

// ---------------- global scratch (no allocations allowed) ----------------
__device__ float    g_emb[NG * Hn];
__device__ float    g_ihpre[NG * 4 * Hn];
__device__ float    g_h[Bn * Hn];
__device__ unsigned g_barc;

__device__ __forceinline__ float sigmoidf_(float v) { return 1.0f / (1.0f + expf(-v)); }

// =====================================================================
// K1: per-graph embedding. One CTA per graph. CSR (counting sort by dst)
// built once in SMEM; all aggregations are atomic-free gather/reduce.
// =====================================================================
__global__ __launch_bounds__(NT) void k_embed(
    const float* __restrict__ x, const int* __restrict__ ei,
    const float* __restrict__ W1, const float* __restrict__ b1,
    const float* __restrict__ Wl, const float* __restrict__ Wr,
    const float* __restrict__ sb,
    const float* __restrict__ W2, const float* __restrict__ b2)
{
    extern __shared__ float sm[];
    // all bases multiples of 4 floats (16B) for float4 access
    float*              A      = sm;                                   // 16384
    float*              Bf     = sm + 16384;                           // 16384
    unsigned long long* keys   = (unsigned long long*)(sm + 32768);    // 1024 u64
    unsigned short*     srcs   = (unsigned short*)(sm + 34816);        // 16384 u16
    int*                off    = (int*)(sm + 43008);                   // 1025 (+pad)
    int*                cur    = (int*)(sm + 44036);                   // 1024
    float*              dinv   = sm + 45060;                           // 1024
    float*              score  = sm + 46084;                           // 1024
    int*                newidx = (int*)(sm + 47108);                   // 1024
    float*              dinv2  = sm + 48132;                           // 1024
    float*              w1s    = sm + 49156;                           // 2048
    float*              w2s    = sm + 51204;                           // 4096
    float*              b2s    = sm + 55300;                           // 256
    float*              cst    = sm + 55556;                           // 64
    float*              red    = sm + 55620;                           // 256

    const int tid = threadIdx.x;
    const int g   = blockIdx.x;
    const float* xg   = x  + (size_t)g * Nn * Fin;
    const int*   srcp = ei + (size_t)g * 2 * En;
    const int*   dstp = srcp + En;

    // --- preload weights, zero histogram -----------------------------------
    for (int i = tid; i < Fin * 16; i += NT) w1s[i] = W1[i];
    for (int i = tid; i < 16 * Hn;  i += NT) w2s[i] = W2[i];
    for (int i = tid; i < Hn;       i += NT) b2s[i] = b2[i];
    if (tid < 16) { cst[tid] = b1[tid]; cst[16 + tid] = Wl[tid]; cst[32 + tid] = Wr[tid]; }
    if (tid == 0) cst[48] = sb[0];
    for (int i = tid; i < Nn; i += NT) cur[i] = 0;
    __syncthreads();

    // --- histogram of dst (int atomics; also gives conv1 degree) -----------
    for (int e = tid; e < En; e += NT) atomicAdd(&cur[dstp[e]], 1);

    // --- conv1 matmul: A = x @ W1  [1024,128]x[128,16] (overlaps histogram)
    {
        const int mq = tid & 3;
        const int nb = tid >> 2;
        for (int n = nb; n < Nn; n += NT / 4) {
            float a0 = 0.f, a1 = 0.f, a2 = 0.f, a3 = 0.f;
            const float4* xr = (const float4*)(xg + (size_t)n * Fin);
            #pragma unroll
            for (int f4 = 0; f4 < Fin / 4; f4++) {
                float4 xv = xr[f4];
                const int fb = f4 * 4;
                float4 q0 = *(const float4*)&w1s[(fb + 0) * 16 + mq * 4];
                float4 q1 = *(const float4*)&w1s[(fb + 1) * 16 + mq * 4];
                float4 q2 = *(const float4*)&w1s[(fb + 2) * 16 + mq * 4];
                float4 q3 = *(const float4*)&w1s[(fb + 3) * 16 + mq * 4];
                a0 += xv.x * q0.x + xv.y * q1.x + xv.z * q2.x + xv.w * q3.x;
                a1 += xv.x * q0.y + xv.y * q1.y + xv.z * q2.y + xv.w * q3.y;
                a2 += xv.x * q0.z + xv.y * q1.z + xv.z * q2.z + xv.w * q3.z;
                a3 += xv.x * q0.w + xv.y * q1.w + xv.z * q2.w + xv.w * q3.w;
            }
            *(float4*)&A[n * 16 + mq * 4] = make_float4(a0, a1, a2, a3);
        }
    }
    __syncthreads();

    // --- exclusive Blelloch scan of counts -> off[0..1024] -----------------
    for (int i = tid; i < Nn; i += NT) off[i] = cur[i];
    for (int d2 = 1; d2 < Nn; d2 <<= 1) {
        __syncthreads();
        const int idx = (tid + 1) * (d2 << 1) - 1;
        if (idx < Nn) off[idx] += off[idx - d2];
    }
    __syncthreads();
    if (tid == 0) { off[Nn] = off[Nn - 1]; off[Nn - 1] = 0; }
    for (int d2 = Nn >> 1; d2 >= 1; d2 >>= 1) {
        __syncthreads();
        const int idx = (tid + 1) * (d2 << 1) - 1;
        if (idx < Nn) { const int t = off[idx - d2]; off[idx - d2] = off[idx]; off[idx] += t; }
    }
    __syncthreads();

    // --- cur = running cursor; dinv from degree -----------------------------
    for (int i = tid; i < Nn; i += NT) {
        cur[i]  = off[i];
        dinv[i] = rsqrtf(1.0f + (float)(off[i + 1] - off[i]));
    }
    __syncthreads();

    // --- placement: srcs sorted by dst (int atomics on cursors) ------------
    for (int e = tid; e < En; e += NT) {
        const int pos = atomicAdd(&cur[dstp[e]], 1);
        srcs[pos] = (unsigned short)srcp[e];
    }
    __syncthreads();

    // --- conv1 gather + self + bias + relu -> Bf = h1 -----------------------
    {
        const int grp = tid >> 2, q = tid & 3;
        const float bx = cst[q * 4 + 0], by = cst[q * 4 + 1];
        const float bz = cst[q * 4 + 2], bw = cst[q * 4 + 3];
        for (int d = grp; d < Nn; d += NT / 4) {
            const int e0 = off[d], e1 = off[d + 1];
            float ax = 0.f, ay = 0.f, az = 0.f, aw = 0.f;
            for (int j = e0; j < e1; j++) {
                const int s = srcs[j];
                const float w = dinv[s];
                const float4 v = *(const float4*)&A[s * 16 + q * 4];
                ax = fmaf(v.x, w, ax); ay = fmaf(v.y, w, ay);
                az = fmaf(v.z, w, az); aw = fmaf(v.w, w, aw);
            }
            const float dd = dinv[d], dd2 = dd * dd;
            const float4 sv = *(const float4*)&A[d * 16 + q * 4];
            float4 o;
            o.x = fmaxf(fmaf(ax, dd, fmaf(sv.x, dd2, bx)), 0.f);
            o.y = fmaxf(fmaf(ay, dd, fmaf(sv.y, dd2, by)), 0.f);
            o.z = fmaxf(fmaf(az, dd, fmaf(sv.z, dd2, bz)), 0.f);
            o.w = fmaxf(fmaf(aw, dd, fmaf(sv.w, dd2, bw)), 0.f);
            *(float4*)&Bf[d * 16 + q * 4] = o;
        }
    }
    __syncthreads();

    // --- SAG aggregate (plain sum of neighbors) -> A = agg -------------------
    {
        const int grp = tid >> 2, q = tid & 3;
        for (int d = grp; d < Nn; d += NT / 4) {
            const int e0 = off[d], e1 = off[d + 1];
            float ax = 0.f, ay = 0.f, az = 0.f, aw = 0.f;
            for (int j = e0; j < e1; j++) {
                const float4 v = *(const float4*)&Bf[srcs[j] * 16 + q * 4];
                ax += v.x; ay += v.y; az += v.z; aw += v.w;
            }
            *(float4*)&A[d * 16 + q * 4] = make_float4(ax, ay, az, aw);
        }
    }
    __syncthreads();

    // --- score + sortable key (A=agg with Wl, Bf=h1 with Wr) -----------------
    for (int n = tid; n < Nn; n += NT) {
        float sc = cst[48];
        #pragma unroll
        for (int m = 0; m < 16; m++)
            sc += A[n * 16 + m] * cst[16 + m] + Bf[n * 16 + m] * cst[32 + m];
        score[n] = sc;
        unsigned u = __float_as_uint(sc);
        u = (u & 0x80000000u) ? ~u : (u | 0x80000000u);
        keys[n] = ((unsigned long long)(~u) << 32) | (unsigned)n;
    }
    __syncthreads();

    // --- bitonic sort (ascending key = descending score, tie -> low idx) -----
    for (int k = 2; k <= Nn; k <<= 1) {
        for (int j = k >> 1; j > 0; j >>= 1) {
            const int i  = tid;
            const int lo = ((i & ~(j - 1)) << 1) | (i & (j - 1));
            const int hi = lo + j;
            const unsigned long long a = keys[lo], b = keys[hi];
            const bool up = ((lo & k) == 0);
            if (up ? (a > b) : (a < b)) { keys[lo] = b; keys[hi] = a; }
            __syncthreads();
        }
    }

    // --- newidx, gated xp -> A rows [0,K) -------------------------------------
    for (int n = tid; n < Nn; n += NT) newidx[n] = -1;
    __syncthreads();
    for (int r = tid; r < Kn; r += NT)
        newidx[(int)(keys[r] & 0xFFFFFFFFull)] = r;
    __syncthreads();
    for (int i = tid; i < Kn * 16; i += NT) {
        const int r = i >> 4, m = i & 15;
        const int n = (int)(keys[r] & 0xFFFFFFFFull);
        A[r * 16 + m] = Bf[n * 16 + m] * tanhf(score[n]);
    }
    __syncthreads();

    // --- deg2: count valid (kept->kept) in-edges per kept node ---------------
    for (int d = tid; d < Nn; d += NT) {
        const int nd = newidx[d];
        if (nd >= 0) {
            int c = 0;
            const int e0 = off[d], e1 = off[d + 1];
            for (int j = e0; j < e1; j++) c += (newidx[srcs[j]] >= 0);
            dinv2[nd] = rsqrtf(1.0f + (float)c);
        }
    }
    __syncthreads();

    // --- conv2 pre-aggregation (MID space) -> Bf rows [0,K) -------------------
    {
        const int grp = tid >> 2, q = tid & 3;
        for (int d = grp; d < Nn; d += NT / 4) {
            const int nd = newidx[d];
            if (nd < 0) continue;
            const int e0 = off[d], e1 = off[d + 1];
            float ax = 0.f, ay = 0.f, az = 0.f, aw = 0.f;
            for (int j = e0; j < e1; j++) {
                const int ns = newidx[srcs[j]];
                if (ns >= 0) {
                    const float w = dinv2[ns];
                    const float4 v = *(const float4*)&A[ns * 16 + q * 4];
                    ax = fmaf(v.x, w, ax); ay = fmaf(v.y, w, ay);
                    az = fmaf(v.z, w, az); aw = fmaf(v.w, w, aw);
                }
            }
            const float dd = dinv2[nd], dd2 = dd * dd;
            const float4 sv = *(const float4*)&A[nd * 16 + q * 4];
            float4 o;
            o.x = fmaf(ax, dd, sv.x * dd2);
            o.y = fmaf(ay, dd, sv.y * dd2);
            o.z = fmaf(az, dd, sv.z * dd2);
            o.w = fmaf(aw, dd, sv.w * dd2);
            *(float4*)&Bf[nd * 16 + q * 4] = o;
        }
    }
    __syncthreads();

    // --- h2 = relu(pre @ W2 + b2), mean over K -> g_emb -----------------------
    {
        const int c    = tid & 255;
        const int half = tid >> 8;
        float wc[16];
        #pragma unroll
        for (int m = 0; m < 16; m++) wc[m] = w2s[m * Hn + c];
        const float bias = b2s[c];
        float acc = 0.f;
        for (int r = half; r < Kn; r += 2) {
            const float4* pr4 = (const float4*)&Bf[r * 16];
            float4 p0 = pr4[0], p1 = pr4[1], p2 = pr4[2], p3 = pr4[3];
            float v = bias
                + p0.x * wc[0]  + p0.y * wc[1]  + p0.z * wc[2]  + p0.w * wc[3]
                + p1.x * wc[4]  + p1.y * wc[5]  + p1.z * wc[6]  + p1.w * wc[7]
                + p2.x * wc[8]  + p2.y * wc[9]  + p2.z * wc[10] + p2.w * wc[11]
                + p3.x * wc[12] + p3.y * wc[13] + p3.z * wc[14] + p3.w * wc[15];
            acc += v > 0.f ? v : 0.f;
        }
        if (half == 1) red[c] = acc;
        __syncthreads();
        if (half == 0) g_emb[(size_t)g * Hn + c] = (acc + red[c]) * (1.0f / (float)Kn);
    }
}

// =====================================================================
// K2: ih_pre = emb @ W_ih^T + b_ih + b_hh ; reset LSTM state + barrier
// =====================================================================
__global__ __launch_bounds__(256) void k_prep(
    const float* __restrict__ W_ih, const float* __restrict__ b_ih,
    const float* __restrict__ b_hh)
{
    __shared__ float es[Hn];
    const int tid = threadIdx.x, g = blockIdx.x;
    es[tid] = g_emb[(size_t)g * Hn + tid];
    __syncthreads();
    const int warp = tid >> 5, lane = tid & 31;
    for (int j = warp; j < 4 * Hn; j += 8) {
        const float* wr = W_ih + (size_t)j * Hn;
        float p = 0.f;
        #pragma unroll 4
        for (int k = lane; k < Hn; k += 32) p += wr[k] * es[k];
        #pragma unroll
        for (int o = 16; o; o >>= 1) p += __shfl_xor_sync(0xFFFFFFFFu, p, o);
        if (lane == 0) g_ihpre[(size_t)g * (4 * Hn) + j] = p + b_ih[j] + b_hh[j];
    }
    if (g == 0) {
        for (int i = tid; i < Bn * Hn; i += 256) g_h[i] = 0.f;
        if (tid == 0) g_barc = 0u;
    }
}

// =====================================================================
// K3: persistent LSTM (64 CTAs, all co-resident) + classifier.
// =====================================================================
__global__ __launch_bounds__(256) void k_lstm(
    const float* __restrict__ W_hh, const float* __restrict__ cls_W,
    const float* __restrict__ cls_b, float* __restrict__ out)
{
    __shared__ float Ws[Hn * 16];
    __shared__ float hs[Hn * 17];
    __shared__ float gsm[256];
    __shared__ float cs[64];
    __shared__ float red[256];
    const int tid = threadIdx.x;
    const int m   = blockIdx.x;

    for (int idx = tid; idx < 16 * Hn; idx += 256) {
        const int q = idx >> 8;
        const int k = idx & 255;
        const int hu_l = q >> 2, gate = q & 3;
        const int j = gate * Hn + (m * 4 + hu_l);
        Ws[k * 16 + q] = W_hh[(size_t)j * Hn + k];
    }
    if (tid < 64) cs[tid] = 0.f;
    __syncthreads();

    const int b = tid & 15, q = tid >> 4;
    const int hu_l = q >> 2, gate = q & 3;
    const int j = gate * Hn + (m * 4 + hu_l);

    for (int t = 0; t < Tn; t++) {
        for (int idx = tid; idx < Bn * Hn; idx += 256) {
            const int bb = idx >> 8, kk = idx & 255;
            hs[kk * 17 + bb] = __ldcg(&g_h[idx]);
        }
        __syncthreads();

        float acc = g_ihpre[(size_t)(t * Bn + b) * (4 * Hn) + j];
        #pragma unroll 8
        for (int k = 0; k < Hn; k++) acc += Ws[k * 16 + q] * hs[k * 17 + b];
        gsm[b * 16 + q] = acc;
        __syncthreads();

        if (tid < 64) {
            const int bb = tid & 15, hl = tid >> 4;
            const float gi = gsm[bb * 16 + hl * 4 + 0];
            const float gf = gsm[bb * 16 + hl * 4 + 1];
            const float gg = gsm[bb * 16 + hl * 4 + 2];
            const float go = gsm[bb * 16 + hl * 4 + 3];
            float cc = cs[tid];
            cc = sigmoidf_(gf) * cc + sigmoidf_(gi) * tanhf(gg);
            cs[tid] = cc;
            __stcg(&g_h[bb * Hn + (m * 4 + hl)], sigmoidf_(go) * tanhf(cc));
        }
        __syncthreads();

        if (tid == 0) {
            __threadfence();
            atomicAdd(&g_barc, 1u);
            const unsigned target = 64u * (unsigned)(t + 1);
            unsigned v;
            do {
                asm volatile("ld.global.acquire.gpu.u32 %0, [%1];" : "=r"(v) : "l"(&g_barc));
                if (v < target) __nanosleep(64);
            } while (v < target);
        }
        __syncthreads();
    }

    if (m == 0) {
        const float w = cls_W[tid];
        for (int bb = 0; bb < Bn; bb++) {
            red[tid] = __ldcg(&g_h[bb * Hn + tid]) * w;
            __syncthreads();
            for (int off = 128; off; off >>= 1) {
                if (tid < off) red[tid] += red[tid + off];
                __syncthreads();
            }
            if (tid == 0) out[bb] = red[0] + cls_b[0];
            __syncthreads();
        }
    }
}

// =====================================================================
extern "C" void kernel_launch(void* const* d_in, const int* in_sizes, int n_in,
                              void* d_out, int out_size)
{
    (void)in_sizes; (void)n_in; (void)out_size;
    const float* x     = (const float*)d_in[0];
    const int*   ei    = (const int*)  d_in[1];
    const float* W1    = (const float*)d_in[2];
    const float* b1    = (const float*)d_in[3];
    const float* Wl    = (const float*)d_in[4];
    const float* Wr    = (const float*)d_in[5];
    const float* sb    = (const float*)d_in[6];
    const float* W2    = (const float*)d_in[7];
    const float* b2    = (const float*)d_in[8];
    const float* W_ih  = (const float*)d_in[9];
    const float* W_hh  = (const float*)d_in[10];
    const float* b_ih  = (const float*)d_in[11];
    const float* b_hh  = (const float*)d_in[12];
    const float* cls_W = (const float*)d_in[13];
    const float* cls_b = (const float*)d_in[14];
    float* out = (float*)d_out;

    const size_t smem = 55876 * sizeof(float);  // 223504 B
    cudaFuncSetAttribute(k_embed, cudaFuncAttributeMaxDynamicSharedMemorySize, (int)smem);

    k_embed<<<NG, NT, smem>>>(x, ei, W1, b1, Wl, Wr, sb, W2, b2);
    k_prep <<<NG, 256>>>(W_ih, b_ih, b_hh);
    k_lstm <<<64, 256>>>(W_hh, cls_W, cls_b, out);
}

// round 5
// speedup vs baseline: 1.0321x; 1.0321x over previous
#include <cuda_runtime.h>
#include <cstdint>

#define NT 512
constexpr int Tn  = 16;
constexpr int Bn  = 16;
constexpr int Nn  = 1024;
constexpr int En  = 16384;
constexpr int Fin = 128;
constexpr int Hn  = 256;
constexpr int Kn  = 820;
constexpr int NG  = Tn * Bn;   // 256 graphs

// ---------------- global scratch ----------------
__device__ float    g_emb[NG * Hn];
__device__ float    g_hb[2][Bn * Hn];   // double-buffered LSTM hidden state
__device__ unsigned g_barc16[Tn];       // per-step barrier counters (reset in k_embed)

__device__ __forceinline__ float sigmoidf_(float v) { return 1.0f / (1.0f + expf(-v)); }

// ---------------- f32x2 helpers ----------------
__device__ __forceinline__ unsigned long long pk2(float a, float b) {
    unsigned long long r; asm("mov.b64 %0,{%1,%2};" : "=l"(r) : "f"(a), "f"(b)); return r;
}
__device__ __forceinline__ float2 upk(unsigned long long v) {
    float2 o; asm("mov.b64 {%0,%1},%2;" : "=f"(o.x), "=f"(o.y) : "l"(v)); return o;
}
__device__ __forceinline__ unsigned long long ffma2(unsigned long long a, unsigned long long b, unsigned long long c) {
    unsigned long long d; asm("fma.rn.f32x2 %0,%1,%2,%3;" : "=l"(d) : "l"(a), "l"(b), "l"(c)); return d;
}
__device__ __forceinline__ float hsum2(unsigned long long v) { float2 o = upk(v); return o.x + o.y; }

// conv1 half: 256 threads (gt in [0,256)), nodes [pb, pb+512)
__device__ __forceinline__ void conv1_half(const float* __restrict__ xg,
                                           const float* w1s, float* A, int gt, int pb)
{
    const int mq = gt & 3;
    const int nb = gt >> 2;
    for (int n = pb + nb; n < pb + 512; n += 64) {
        float a0 = 0.f, a1 = 0.f, a2 = 0.f, a3 = 0.f;
        const float4* xr = (const float4*)(xg + (size_t)n * Fin);
        #pragma unroll
        for (int f4 = 0; f4 < Fin / 4; f4++) {
            float4 xv = xr[f4];
            const int fb = f4 * 4;
            float4 q0 = *(const float4*)&w1s[(fb + 0) * 16 + mq * 4];
            float4 q1 = *(const float4*)&w1s[(fb + 1) * 16 + mq * 4];
            float4 q2 = *(const float4*)&w1s[(fb + 2) * 16 + mq * 4];
            float4 q3 = *(const float4*)&w1s[(fb + 3) * 16 + mq * 4];
            a0 += xv.x * q0.x + xv.y * q1.x + xv.z * q2.x + xv.w * q3.x;
            a1 += xv.x * q0.y + xv.y * q1.y + xv.z * q2.y + xv.w * q3.y;
            a2 += xv.x * q0.z + xv.y * q1.z + xv.z * q2.z + xv.w * q3.z;
            a3 += xv.x * q0.w + xv.y * q1.w + xv.z * q2.w + xv.w * q3.w;
        }
        *(float4*)&A[n * 16 + mq * 4] = make_float4(a0, a1, a2, a3);
    }
}

// =====================================================================
// K1: per-graph embedding. One CTA per graph.
// =====================================================================
__global__ __launch_bounds__(NT) void k_embed(
    const float* __restrict__ x, const int* __restrict__ ei,
    const float* __restrict__ W1, const float* __restrict__ b1,
    const float* __restrict__ Wl, const float* __restrict__ Wr,
    const float* __restrict__ sb,
    const float* __restrict__ W2, const float* __restrict__ b2)
{
    extern __shared__ float sm[];
    float*              A      = sm;                                 // [0,16384)
    float*              Bf     = sm + 16384;                         // [16384,32768)
    unsigned long long* keys   = (unsigned long long*)(sm + 32768);  // 1024 u64 [32768,34816)
    unsigned short*     srcs   = (unsigned short*)(sm + 34816);      // 16384 u16 [34816,43008)
    int*                off    = (int*)(sm + 43008);                 // 1028 [43008,44036)
    int*                cur    = (int*)(sm + 44036);                 // 1024 [44036,45060)
    float*              pv     = sm + 45060;                         // 1024 (dinv, then p)
    float*              score  = sm + 46084;                         // 1024
    int*                newidx = (int*)(sm + 47108);                 // 1024
    float*              dinv2  = sm + 48132;                         // 1024
    float*              w1s    = sm + 49156;                         // 2048 [49156,51204)
    float*              w2s    = sm + 51204;                         // 4096 (aliases tmppos)
    unsigned char*      tmppos = (unsigned char*)(sm + 51204);       // 16384 u8 [51204,55300)
    float*              b2s    = sm + 55300;                         // 256
    float*              cst    = sm + 55556;                         // 64
    // total 55620 floats = 222480 B

    const int tid = threadIdx.x;
    const int g   = blockIdx.x;
    const float* xg   = x  + (size_t)g * Nn * Fin;
    const int*   srcp = ei + (size_t)g * 2 * En;
    const int*   dstp = srcp + En;

    for (int i = tid; i < Fin * 16; i += NT) w1s[i] = W1[i];
    if (tid < 16) { cst[tid] = b1[tid]; cst[16 + tid] = Wl[tid]; cst[32 + tid] = Wr[tid]; }
    if (tid == 0) cst[48] = sb[0];
    for (int i = tid; i < Nn; i += NT) cur[i] = 0;
    if (g == 0) {
        for (int i = tid; i < 2 * Bn * Hn; i += NT) ((float*)g_hb)[i] = 0.f;
        if (tid < Tn) g_barc16[tid] = 0u;
    }
    __syncthreads();

    // --- phase A: warps 0-7 conv1 nodes [0,512) || warps 8-15 histogram+rank
    if (tid < 256) {
        conv1_half(xg, w1s, A, tid, 0);
    } else {
        for (int e = tid - 256; e < En; e += 256)
            tmppos[e] = (unsigned char)atomicAdd(&cur[dstp[e]], 1);
    }
    __syncthreads();

    // --- exclusive Blelloch scan of counts -> off[0..1024] ------------------
    for (int i = tid; i < Nn; i += NT) off[i] = cur[i];
    for (int d2 = 1; d2 < Nn; d2 <<= 1) {
        __syncthreads();
        const int idx = (tid + 1) * (d2 << 1) - 1;
        if (idx < Nn) off[idx] += off[idx - d2];
    }
    __syncthreads();
    if (tid == 0) { off[Nn] = off[Nn - 1]; off[Nn - 1] = 0; }
    for (int d2 = Nn >> 1; d2 >= 1; d2 >>= 1) {
        __syncthreads();
        const int idx = (tid + 1) * (d2 << 1) - 1;
        if (idx < Nn) { const int t = off[idx - d2]; off[idx - d2] = off[idx]; off[idx] += t; }
    }
    __syncthreads();
    for (int i = tid; i < Nn; i += NT)
        pv[i] = rsqrtf(1.0f + (float)(off[i + 1] - off[i]));   // dinv
    __syncthreads();

    // --- phase C: warps 0-7 conv1 nodes [512,1024) || warps 8-15 placement --
    if (tid < 256) {
        conv1_half(xg, w1s, A, tid, 512);
    } else {
        for (int e = tid - 256; e < En; e += 256)
            srcs[off[dstp[e]] + tmppos[e]] = (unsigned short)srcp[e];
    }
    __syncthreads();

    // tmppos dead -> load W2/b2 into its alias; pre-scale A rows by dinv
    for (int i = tid; i < 16 * Hn; i += NT) w2s[i] = W2[i];
    for (int i = tid; i < Hn; i += NT) b2s[i] = b2[i];
    for (int i = tid; i < Nn * 16; i += NT) A[i] *= pv[i >> 4];
    __syncthreads();

    // --- conv1 gather (pure sum, self included) + bias + relu -> Bf = h1 ----
    {
        const int grp = tid >> 2, q = tid & 3;
        const float bx = cst[q * 4 + 0], by = cst[q * 4 + 1];
        const float bz = cst[q * 4 + 2], bw = cst[q * 4 + 3];
        for (int d = grp; d < Nn; d += 128) {
            const int e0 = off[d], e1 = off[d + 1];
            float4 ac = *(const float4*)&A[d * 16 + q * 4];   // self (scaled)
            for (int j = e0; j < e1; j++) {
                const float4 v = *(const float4*)&A[srcs[j] * 16 + q * 4];
                ac.x += v.x; ac.y += v.y; ac.z += v.z; ac.w += v.w;
            }
            const float dd = pv[d];
            float4 o;
            o.x = fmaxf(fmaf(ac.x, dd, bx), 0.f);
            o.y = fmaxf(fmaf(ac.y, dd, by), 0.f);
            o.z = fmaxf(fmaf(ac.z, dd, bz), 0.f);
            o.w = fmaxf(fmaf(ac.w, dd, bw), 0.f);
            *(float4*)&Bf[d * 16 + q * 4] = o;
        }
    }
    __syncthreads();

    // --- p[n] = h1[n].Wl ; score[n] = h1[n].Wr + sag_b ----------------------
    for (int n = tid; n < Nn; n += NT) {
        float pl = 0.f, pr = cst[48];
        #pragma unroll
        for (int m = 0; m < 16; m++) {
            const float h = Bf[n * 16 + m];
            pl = fmaf(h, cst[16 + m], pl);
            pr = fmaf(h, cst[32 + m], pr);
        }
        pv[n] = pl; score[n] = pr;
    }
    __syncthreads();

    // --- score[d] += sum p[srcs] ; sortable keys ------------------------------
    for (int d = tid; d < Nn; d += NT) {
        float s = score[d];
        const int e0 = off[d], e1 = off[d + 1];
        for (int j = e0; j < e1; j++) s += pv[srcs[j]];
        score[d] = s;
        unsigned u = __float_as_uint(s);
        u = (u & 0x80000000u) ? ~u : (u | 0x80000000u);
        keys[d] = ((unsigned long long)(~u) << 32) | (unsigned)d;
    }
    __syncthreads();

    // --- bitonic sort ----------------------------------------------------------
    for (int k = 2; k <= Nn; k <<= 1) {
        for (int j = k >> 1; j > 0; j >>= 1) {
            const int lo = ((tid & ~(j - 1)) << 1) | (tid & (j - 1));
            const int hi = lo + j;
            const unsigned long long a = keys[lo], b = keys[hi];
            const bool up = ((lo & k) == 0);
            if (up ? (a > b) : (a < b)) { keys[lo] = b; keys[hi] = a; }
            __syncthreads();
        }
    }

    // --- newidx + gate -----------------------------------------------------------
    for (int n = tid; n < Nn; n += NT) newidx[n] = -1;
    __syncthreads();
    float* tvf = (float*)cur;
    for (int r = tid; r < Kn; r += NT) {
        const int n = (int)(keys[r] & 0xFFFFFFFFull);
        newidx[n] = r;
        tvf[r] = tanhf(score[n]);
    }
    __syncthreads();
    for (int i = tid; i < Kn * 16; i += NT) {
        const int r = i >> 4, m = i & 15;
        const int n = (int)(keys[r] & 0xFFFFFFFFull);
        A[r * 16 + m] = Bf[n * 16 + m] * tvf[r];
    }
    __syncthreads();

    // --- deg2 over valid remapped edges -----------------------------------------
    for (int d = tid; d < Nn; d += NT) {
        const int nd = newidx[d];
        if (nd >= 0) {
            int c = 0;
            const int e0 = off[d], e1 = off[d + 1];
            for (int j = e0; j < e1; j++) c += (newidx[srcs[j]] >= 0);
            dinv2[nd] = rsqrtf(1.0f + (float)c);
        }
    }
    __syncthreads();
    for (int i = tid; i < Kn * 16; i += NT) A[i] *= dinv2[i >> 4];   // pre-scale xp
    __syncthreads();

    // --- conv2 pre-aggregation (MID space) -> Bf rows [0,K) ----------------------
    {
        const int grp = tid >> 2, q = tid & 3;
        for (int d = grp; d < Nn; d += 128) {
            const int nd = newidx[d];
            if (nd < 0) continue;
            const int e0 = off[d], e1 = off[d + 1];
            float4 ac = *(const float4*)&A[nd * 16 + q * 4];   // self (scaled)
            for (int j = e0; j < e1; j++) {
                const int ns = newidx[srcs[j]];
                if (ns >= 0) {
                    const float4 v = *(const float4*)&A[ns * 16 + q * 4];
                    ac.x += v.x; ac.y += v.y; ac.z += v.z; ac.w += v.w;
                }
            }
            const float dd = dinv2[nd];
            *(float4*)&Bf[nd * 16 + q * 4] = make_float4(ac.x * dd, ac.y * dd, ac.z * dd, ac.w * dd);
        }
    }
    __syncthreads();

    // --- h2 = relu(pre @ W2 + b2), mean over K -> g_emb (f32x2, regs) ------------
    {
        const int cg = tid & 63, rb = tid >> 6;
        const int c0 = cg * 4;
        unsigned long long wreg[32];
        #pragma unroll
        for (int i = 0; i < 4; i++)
            #pragma unroll
            for (int k2 = 0; k2 < 8; k2++)
                wreg[i * 8 + k2] = pk2(w2s[(2 * k2) * Hn + c0 + i], w2s[(2 * k2 + 1) * Hn + c0 + i]);
        float biasv[4], accs[4];
        #pragma unroll
        for (int i = 0; i < 4; i++) { biasv[i] = b2s[c0 + i]; accs[i] = 0.f; }

        for (int r = rb; r < Kn; r += 8) {
            const ulonglong2* pr = (const ulonglong2*)&Bf[r * 16];
            const ulonglong2 v0 = pr[0], v1 = pr[1], v2 = pr[2], v3 = pr[3];
            #pragma unroll
            for (int i = 0; i < 4; i++) {
                unsigned long long dd_ = 0;
                dd_ = ffma2(v0.x, wreg[i * 8 + 0], dd_);
                dd_ = ffma2(v0.y, wreg[i * 8 + 1], dd_);
                dd_ = ffma2(v1.x, wreg[i * 8 + 2], dd_);
                dd_ = ffma2(v1.y, wreg[i * 8 + 3], dd_);
                dd_ = ffma2(v2.x, wreg[i * 8 + 4], dd_);
                dd_ = ffma2(v2.y, wreg[i * 8 + 5], dd_);
                dd_ = ffma2(v3.x, wreg[i * 8 + 6], dd_);
                dd_ = ffma2(v3.y, wreg[i * 8 + 7], dd_);
                accs[i] += fmaxf(hsum2(dd_) + biasv[i], 0.f);
            }
        }
        float* redf = (float*)keys;   // keys dead
        #pragma unroll
        for (int i = 0; i < 4; i++) redf[rb * 256 + c0 + i] = accs[i];
        __syncthreads();
        if (tid < 256) {
            float s = 0.f;
            #pragma unroll
            for (int rbi = 0; rbi < 8; rbi++) s += redf[rbi * 256 + tid];
            g_emb[(size_t)g * Hn + tid] = s * (1.0f / (float)Kn);
        }
    }
}

// =====================================================================
// K2: fused ihpre + persistent LSTM (64 co-resident CTAs) + classifier.
// =====================================================================
__global__ __launch_bounds__(256) void k_lstm(
    const float* __restrict__ W_ih, const float* __restrict__ b_ih,
    const float* __restrict__ b_hh, const float* __restrict__ W_hh,
    const float* __restrict__ cls_W, const float* __restrict__ cls_b,
    float* __restrict__ out)
{
    extern __shared__ float s[];
    float* Ws   = s;            // 16*260  [q][k]
    float* ihs  = s + 4160;     // 4096    [g][q]
    float* hsb  = s + 8256;     // 16*260  [b][k]
    float* wih  = s + 12416;    // 4096    [q][k]
    float* embt = s + 16512;    // 4096
    float* gsm  = s + 20608;    // 256
    float* cs   = s + 20864;    // 64
    float* bsm  = s + 20928;    // 16
    float* red  = s + 20944;    // 256
    // total 21200 floats = 84800 B

    const int tid = threadIdx.x;
    const int m   = blockIdx.x;   // 0..63

    for (int idx = tid; idx < 16 * Hn; idx += 256) {
        const int q = idx >> 8, k = idx & 255;
        const int j = (q & 3) * Hn + m * 4 + (q >> 2);
        Ws[q * 260 + k]  = W_hh[(size_t)j * Hn + k];
        wih[q * 256 + k] = W_ih[(size_t)j * Hn + k];
    }
    if (tid < 16) {
        const int j = (tid & 3) * Hn + m * 4 + (tid >> 2);
        bsm[tid] = b_ih[j] + b_hh[j];
    }
    if (tid < 64) cs[tid] = 0.f;
    __syncthreads();

    // --- prologue: ihs[g][q] = emb[g] . W_ih[j(q)] + bias, 16-graph tiles ---
    for (int tile = 0; tile < 16; tile++) {
        const int gb = tile * 16;
        for (int idx = tid; idx < 4096; idx += 256)
            embt[idx] = g_emb[(size_t)gb * Hn + idx];
        __syncthreads();
        const int gl = tid >> 4, q = tid & 15;
        float acc = bsm[q];
        const float4* ev = (const float4*)&embt[gl * 256];
        const float4* wv = (const float4*)&wih[q * 256];
        #pragma unroll 8
        for (int k4 = 0; k4 < 64; k4++) {
            const float4 e = ev[k4], w = wv[k4];
            acc += e.x * w.x + e.y * w.y + e.z * w.z + e.w * w.w;
        }
        ihs[(gb + gl) * 16 + q] = acc;
        __syncthreads();
    }

    const int b = tid & 15, q = tid >> 4;

    for (int t = 0; t < Tn; t++) {
        const float* hsrc = g_hb[t & 1];
        for (int idx = tid; idx < Bn * Hn; idx += 256)
            hsb[(idx >> 8) * 260 + (idx & 255)] = __ldcg(&hsrc[idx]);
        __syncthreads();

        float acc = ihs[(t * 16 + b) * 16 + q];
        const float4* hv = (const float4*)&hsb[b * 260];
        const float4* wv = (const float4*)&Ws[q * 260];
        #pragma unroll 8
        for (int k4 = 0; k4 < 64; k4++) {
            const float4 h4 = hv[k4], w4 = wv[k4];
            acc += h4.x * w4.x + h4.y * w4.y + h4.z * w4.z + h4.w * w4.w;
        }
        gsm[b * 16 + q] = acc;
        __syncthreads();

        if (tid < 64) {
            const int bb = tid & 15, hl = tid >> 4;
            const float gi = gsm[bb * 16 + hl * 4 + 0];
            const float gf = gsm[bb * 16 + hl * 4 + 1];
            const float gg = gsm[bb * 16 + hl * 4 + 2];
            const float go = gsm[bb * 16 + hl * 4 + 3];
            float cc = cs[tid];
            cc = sigmoidf_(gf) * cc + sigmoidf_(gi) * tanhf(gg);
            cs[tid] = cc;
            __stcg(&g_hb[(t + 1) & 1][bb * Hn + m * 4 + hl], sigmoidf_(go) * tanhf(cc));
        }
        __syncthreads();

        if (tid == 0) {
            __threadfence();
            atomicAdd(&g_barc16[t], 1u);
            unsigned v;
            do {
                asm volatile("ld.global.acquire.gpu.u32 %0,[%1];" : "=r"(v) : "l"(&g_barc16[t]));
            } while (v < 64u);
        }
        __syncthreads();
    }

    // classifier on CTA 0: out[b] = h_T[b] . cls_W + cls_b (final h in g_hb[0])
    if (m == 0) {
        const float w = cls_W[tid];
        for (int bb = 0; bb < Bn; bb++) {
            red[tid] = __ldcg(&g_hb[0][bb * Hn + tid]) * w;
            __syncthreads();
            for (int off = 128; off; off >>= 1) {
                if (tid < off) red[tid] += red[tid + off];
                __syncthreads();
            }
            if (tid == 0) out[bb] = red[0] + cls_b[0];
            __syncthreads();
        }
    }
}

// =====================================================================
extern "C" void kernel_launch(void* const* d_in, const int* in_sizes, int n_in,
                              void* d_out, int out_size)
{
    (void)in_sizes; (void)n_in; (void)out_size;
    const float* x     = (const float*)d_in[0];
    const int*   ei    = (const int*)  d_in[1];
    const float* W1    = (const float*)d_in[2];
    const float* b1    = (const float*)d_in[3];
    const float* Wl    = (const float*)d_in[4];
    const float* Wr    = (const float*)d_in[5];
    const float* sb    = (const float*)d_in[6];
    const float* W2    = (const float*)d_in[7];
    const float* b2    = (const float*)d_in[8];
    const float* W_ih  = (const float*)d_in[9];
    const float* W_hh  = (const float*)d_in[10];
    const float* b_ih  = (const float*)d_in[11];
    const float* b_hh  = (const float*)d_in[12];
    const float* cls_W = (const float*)d_in[13];
    const float* cls_b = (const float*)d_in[14];
    float* out = (float*)d_out;

    const size_t smem1 = 55620 * sizeof(float);  // 222480 B
    const size_t smem2 = 21200 * sizeof(float);  // 84800 B
    cudaFuncSetAttribute(k_embed, cudaFuncAttributeMaxDynamicSharedMemorySize, (int)smem1);
    cudaFuncSetAttribute(k_lstm,  cudaFuncAttributeMaxDynamicSharedMemorySize, (int)smem2);

    k_embed<<<NG, NT, smem1>>>(x, ei, W1, b1, Wl, Wr, sb, W2, b2);
    k_lstm <<<64, 256, smem2>>>(W_ih, b_ih, b_hh, W_hh, cls_W, cls_b, out);
}

// round 6
// speedup vs baseline: 1.1614x; 1.1253x over previous
#include <cuda_runtime.h>
#include <cstdint>

#define NT 512
constexpr int Tn  = 16;
constexpr int Bn  = 16;
constexpr int Nn  = 1024;
constexpr int En  = 16384;
constexpr int Fin = 128;
constexpr int Hn  = 256;
constexpr int Kn  = 820;
constexpr int NG  = Tn * Bn;   // 256 graphs

// ---------------- global scratch ----------------
__device__ float g_emb[NG * Hn];
__device__ float g_ihpre[NG * 4 * Hn];   // [g][j], j = gate*256 + hu

__device__ __forceinline__ float sigmoidf_(float v) { return 1.0f / (1.0f + expf(-v)); }

// ---------------- f32x2 helpers ----------------
__device__ __forceinline__ unsigned long long pk2(float a, float b) {
    unsigned long long r; asm("mov.b64 %0,{%1,%2};" : "=l"(r) : "f"(a), "f"(b)); return r;
}
__device__ __forceinline__ float2 upk(unsigned long long v) {
    float2 o; asm("mov.b64 {%0,%1},%2;" : "=f"(o.x), "=f"(o.y) : "l"(v)); return o;
}
__device__ __forceinline__ unsigned long long ffma2(unsigned long long a, unsigned long long b, unsigned long long c) {
    unsigned long long d; asm("fma.rn.f32x2 %0,%1,%2,%3;" : "=l"(d) : "l"(a), "l"(b), "l"(c)); return d;
}
__device__ __forceinline__ float hsum2(unsigned long long v) { float2 o = upk(v); return o.x + o.y; }

__device__ __forceinline__ uint32_t smem_u32(const void* p) {
    uint32_t a;
    asm("{ .reg .u64 t; cvta.to.shared.u64 t, %1; cvt.u32.u64 %0, t; }" : "=r"(a) : "l"(p));
    return a;
}

#define CLUSTER_SYNC_() do { \
    asm volatile("barrier.cluster.arrive.aligned;" ::: "memory"); \
    asm volatile("barrier.cluster.wait.aligned;" ::: "memory"); \
} while (0)

// conv1 half: 256 threads (gt in [0,256)), nodes [pb, pb+512)
__device__ __forceinline__ void conv1_half(const float* __restrict__ xg,
                                           const float* w1s, float* A, int gt, int pb)
{
    const int mq = gt & 3;
    const int nb = gt >> 2;
    for (int n = pb + nb; n < pb + 512; n += 64) {
        float a0 = 0.f, a1 = 0.f, a2 = 0.f, a3 = 0.f;
        const float4* xr = (const float4*)(xg + (size_t)n * Fin);
        #pragma unroll
        for (int f4 = 0; f4 < Fin / 4; f4++) {
            float4 xv = xr[f4];
            const int fb = f4 * 4;
            float4 q0 = *(const float4*)&w1s[(fb + 0) * 16 + mq * 4];
            float4 q1 = *(const float4*)&w1s[(fb + 1) * 16 + mq * 4];
            float4 q2 = *(const float4*)&w1s[(fb + 2) * 16 + mq * 4];
            float4 q3 = *(const float4*)&w1s[(fb + 3) * 16 + mq * 4];
            a0 += xv.x * q0.x + xv.y * q1.x + xv.z * q2.x + xv.w * q3.x;
            a1 += xv.x * q0.y + xv.y * q1.y + xv.z * q2.y + xv.w * q3.y;
            a2 += xv.x * q0.z + xv.y * q1.z + xv.z * q2.z + xv.w * q3.z;
            a3 += xv.x * q0.w + xv.y * q1.w + xv.z * q2.w + xv.w * q3.w;
        }
        *(float4*)&A[n * 16 + mq * 4] = make_float4(a0, a1, a2, a3);
    }
}

// =====================================================================
// K1: per-graph embedding. One CTA per graph. (verified R5 body)
// =====================================================================
__global__ __launch_bounds__(NT) void k_embed(
    const float* __restrict__ x, const int* __restrict__ ei,
    const float* __restrict__ W1, const float* __restrict__ b1,
    const float* __restrict__ Wl, const float* __restrict__ Wr,
    const float* __restrict__ sb,
    const float* __restrict__ W2, const float* __restrict__ b2)
{
    extern __shared__ float sm[];
    float*              A      = sm;                                 // [0,16384)
    float*              Bf     = sm + 16384;                         // [16384,32768)
    unsigned long long* keys   = (unsigned long long*)(sm + 32768);  // 1024 u64
    unsigned short*     srcs   = (unsigned short*)(sm + 34816);      // 16384 u16
    int*                off    = (int*)(sm + 43008);                 // 1028
    int*                cur    = (int*)(sm + 44036);                 // 1024
    float*              pv     = sm + 45060;                         // 1024
    float*              score  = sm + 46084;                         // 1024
    int*                newidx = (int*)(sm + 47108);                 // 1024
    float*              dinv2  = sm + 48132;                         // 1024
    float*              w1s    = sm + 49156;                         // 2048
    float*              w2s    = sm + 51204;                         // 4096 (aliases tmppos)
    unsigned char*      tmppos = (unsigned char*)(sm + 51204);       // 16384 u8
    float*              b2s    = sm + 55300;                         // 256
    float*              cst    = sm + 55556;                         // 64
    // total 55620 floats = 222480 B

    const int tid = threadIdx.x;
    const int g   = blockIdx.x;
    const float* xg   = x  + (size_t)g * Nn * Fin;
    const int*   srcp = ei + (size_t)g * 2 * En;
    const int*   dstp = srcp + En;

    for (int i = tid; i < Fin * 16; i += NT) w1s[i] = W1[i];
    if (tid < 16) { cst[tid] = b1[tid]; cst[16 + tid] = Wl[tid]; cst[32 + tid] = Wr[tid]; }
    if (tid == 0) cst[48] = sb[0];
    for (int i = tid; i < Nn; i += NT) cur[i] = 0;
    __syncthreads();

    // --- phase A: warps 0-7 conv1 nodes [0,512) || warps 8-15 histogram+rank
    if (tid < 256) {
        conv1_half(xg, w1s, A, tid, 0);
    } else {
        for (int e = tid - 256; e < En; e += 256)
            tmppos[e] = (unsigned char)atomicAdd(&cur[dstp[e]], 1);
    }
    __syncthreads();

    // --- exclusive Blelloch scan of counts -> off[0..1024] ------------------
    for (int i = tid; i < Nn; i += NT) off[i] = cur[i];
    for (int d2 = 1; d2 < Nn; d2 <<= 1) {
        __syncthreads();
        const int idx = (tid + 1) * (d2 << 1) - 1;
        if (idx < Nn) off[idx] += off[idx - d2];
    }
    __syncthreads();
    if (tid == 0) { off[Nn] = off[Nn - 1]; off[Nn - 1] = 0; }
    for (int d2 = Nn >> 1; d2 >= 1; d2 >>= 1) {
        __syncthreads();
        const int idx = (tid + 1) * (d2 << 1) - 1;
        if (idx < Nn) { const int t = off[idx - d2]; off[idx - d2] = off[idx]; off[idx] += t; }
    }
    __syncthreads();
    for (int i = tid; i < Nn; i += NT)
        pv[i] = rsqrtf(1.0f + (float)(off[i + 1] - off[i]));   // dinv
    __syncthreads();

    // --- phase C: warps 0-7 conv1 nodes [512,1024) || warps 8-15 placement --
    if (tid < 256) {
        conv1_half(xg, w1s, A, tid, 512);
    } else {
        for (int e = tid - 256; e < En; e += 256)
            srcs[off[dstp[e]] + tmppos[e]] = (unsigned short)srcp[e];
    }
    __syncthreads();

    // tmppos dead -> load W2/b2 into its alias; pre-scale A rows by dinv
    for (int i = tid; i < 16 * Hn; i += NT) w2s[i] = W2[i];
    for (int i = tid; i < Hn; i += NT) b2s[i] = b2[i];
    for (int i = tid; i < Nn * 16; i += NT) A[i] *= pv[i >> 4];
    __syncthreads();

    // --- conv1 gather (pure sum, self included) + bias + relu -> Bf = h1 ----
    {
        const int grp = tid >> 2, q = tid & 3;
        const float bx = cst[q * 4 + 0], by = cst[q * 4 + 1];
        const float bz = cst[q * 4 + 2], bw = cst[q * 4 + 3];
        for (int d = grp; d < Nn; d += 128) {
            const int e0 = off[d], e1 = off[d + 1];
            float4 ac = *(const float4*)&A[d * 16 + q * 4];   // self (scaled)
            for (int j = e0; j < e1; j++) {
                const float4 v = *(const float4*)&A[srcs[j] * 16 + q * 4];
                ac.x += v.x; ac.y += v.y; ac.z += v.z; ac.w += v.w;
            }
            const float dd = pv[d];
            float4 o;
            o.x = fmaxf(fmaf(ac.x, dd, bx), 0.f);
            o.y = fmaxf(fmaf(ac.y, dd, by), 0.f);
            o.z = fmaxf(fmaf(ac.z, dd, bz), 0.f);
            o.w = fmaxf(fmaf(ac.w, dd, bw), 0.f);
            *(float4*)&Bf[d * 16 + q * 4] = o;
        }
    }
    __syncthreads();

    // --- p[n] = h1[n].Wl ; score[n] = h1[n].Wr + sag_b ----------------------
    for (int n = tid; n < Nn; n += NT) {
        float pl = 0.f, pr = cst[48];
        #pragma unroll
        for (int m = 0; m < 16; m++) {
            const float h = Bf[n * 16 + m];
            pl = fmaf(h, cst[16 + m], pl);
            pr = fmaf(h, cst[32 + m], pr);
        }
        pv[n] = pl; score[n] = pr;
    }
    __syncthreads();

    // --- score[d] += sum p[srcs] ; sortable keys ------------------------------
    for (int d = tid; d < Nn; d += NT) {
        float s = score[d];
        const int e0 = off[d], e1 = off[d + 1];
        for (int j = e0; j < e1; j++) s += pv[srcs[j]];
        score[d] = s;
        unsigned u = __float_as_uint(s);
        u = (u & 0x80000000u) ? ~u : (u | 0x80000000u);
        keys[d] = ((unsigned long long)(~u) << 32) | (unsigned)d;
    }
    __syncthreads();

    // --- bitonic sort ----------------------------------------------------------
    for (int k = 2; k <= Nn; k <<= 1) {
        for (int j = k >> 1; j > 0; j >>= 1) {
            const int lo = ((tid & ~(j - 1)) << 1) | (tid & (j - 1));
            const int hi = lo + j;
            const unsigned long long a = keys[lo], b = keys[hi];
            const bool up = ((lo & k) == 0);
            if (up ? (a > b) : (a < b)) { keys[lo] = b; keys[hi] = a; }
            __syncthreads();
        }
    }

    // --- newidx + gate -----------------------------------------------------------
    for (int n = tid; n < Nn; n += NT) newidx[n] = -1;
    __syncthreads();
    float* tvf = (float*)cur;
    for (int r = tid; r < Kn; r += NT) {
        const int n = (int)(keys[r] & 0xFFFFFFFFull);
        newidx[n] = r;
        tvf[r] = tanhf(score[n]);
    }
    __syncthreads();
    for (int i = tid; i < Kn * 16; i += NT) {
        const int r = i >> 4, m = i & 15;
        const int n = (int)(keys[r] & 0xFFFFFFFFull);
        A[r * 16 + m] = Bf[n * 16 + m] * tvf[r];
    }
    __syncthreads();

    // --- deg2 over valid remapped edges -----------------------------------------
    for (int d = tid; d < Nn; d += NT) {
        const int nd = newidx[d];
        if (nd >= 0) {
            int c = 0;
            const int e0 = off[d], e1 = off[d + 1];
            for (int j = e0; j < e1; j++) c += (newidx[srcs[j]] >= 0);
            dinv2[nd] = rsqrtf(1.0f + (float)c);
        }
    }
    __syncthreads();
    for (int i = tid; i < Kn * 16; i += NT) A[i] *= dinv2[i >> 4];   // pre-scale xp
    __syncthreads();

    // --- conv2 pre-aggregation (MID space) -> Bf rows [0,K) ----------------------
    {
        const int grp = tid >> 2, q = tid & 3;
        for (int d = grp; d < Nn; d += 128) {
            const int nd = newidx[d];
            if (nd < 0) continue;
            const int e0 = off[d], e1 = off[d + 1];
            float4 ac = *(const float4*)&A[nd * 16 + q * 4];   // self (scaled)
            for (int j = e0; j < e1; j++) {
                const int ns = newidx[srcs[j]];
                if (ns >= 0) {
                    const float4 v = *(const float4*)&A[ns * 16 + q * 4];
                    ac.x += v.x; ac.y += v.y; ac.z += v.z; ac.w += v.w;
                }
            }
            const float dd = dinv2[nd];
            *(float4*)&Bf[nd * 16 + q * 4] = make_float4(ac.x * dd, ac.y * dd, ac.z * dd, ac.w * dd);
        }
    }
    __syncthreads();

    // --- h2 = relu(pre @ W2 + b2), mean over K -> g_emb (f32x2, regs) ------------
    {
        const int cg = tid & 63, rb = tid >> 6;
        const int c0 = cg * 4;
        unsigned long long wreg[32];
        #pragma unroll
        for (int i = 0; i < 4; i++)
            #pragma unroll
            for (int k2 = 0; k2 < 8; k2++)
                wreg[i * 8 + k2] = pk2(w2s[(2 * k2) * Hn + c0 + i], w2s[(2 * k2 + 1) * Hn + c0 + i]);
        float biasv[4], accs[4];
        #pragma unroll
        for (int i = 0; i < 4; i++) { biasv[i] = b2s[c0 + i]; accs[i] = 0.f; }

        for (int r = rb; r < Kn; r += 8) {
            const ulonglong2* pr = (const ulonglong2*)&Bf[r * 16];
            const ulonglong2 v0 = pr[0], v1 = pr[1], v2 = pr[2], v3 = pr[3];
            #pragma unroll
            for (int i = 0; i < 4; i++) {
                unsigned long long dd_ = 0;
                dd_ = ffma2(v0.x, wreg[i * 8 + 0], dd_);
                dd_ = ffma2(v0.y, wreg[i * 8 + 1], dd_);
                dd_ = ffma2(v1.x, wreg[i * 8 + 2], dd_);
                dd_ = ffma2(v1.y, wreg[i * 8 + 3], dd_);
                dd_ = ffma2(v2.x, wreg[i * 8 + 4], dd_);
                dd_ = ffma2(v2.y, wreg[i * 8 + 5], dd_);
                dd_ = ffma2(v3.x, wreg[i * 8 + 6], dd_);
                dd_ = ffma2(v3.y, wreg[i * 8 + 7], dd_);
                accs[i] += fmaxf(hsum2(dd_) + biasv[i], 0.f);
            }
        }
        float* redf = (float*)keys;   // keys dead
        #pragma unroll
        for (int i = 0; i < 4; i++) redf[rb * 256 + c0 + i] = accs[i];
        __syncthreads();
        if (tid < 256) {
            float s = 0.f;
            #pragma unroll
            for (int rbi = 0; rbi < 8; rbi++) s += redf[rbi * 256 + tid];
            g_emb[(size_t)g * Hn + tid] = s * (1.0f / (float)Kn);
        }
    }
}

// =====================================================================
// K2: ihpre[g][j] = emb[g].W_ih[j] + b_ih[j] + b_hh[j]; 64 CTAs x 16 rows
// =====================================================================
__global__ __launch_bounds__(256) void k_prep(
    const float* __restrict__ W_ih, const float* __restrict__ b_ih,
    const float* __restrict__ b_hh)
{
    __shared__ float wih[16 * 260];
    __shared__ float embt[16 * 260];
    __shared__ float bs[16];
    const int tid = threadIdx.x;
    const int j0  = blockIdx.x * 16;

    for (int idx = tid; idx < 16 * 256; idx += 256)
        wih[(idx >> 8) * 260 + (idx & 255)] = W_ih[(size_t)(j0 + (idx >> 8)) * Hn + (idx & 255)];
    if (tid < 16) bs[tid] = b_ih[j0 + tid] + b_hh[j0 + tid];
    __syncthreads();

    const int rl = tid & 15, gl = tid >> 4;
    for (int tile = 0; tile < 16; tile++) {
        const int gb = tile * 16;
        for (int idx = tid; idx < 16 * 256; idx += 256)
            embt[(idx >> 8) * 260 + (idx & 255)] = g_emb[(size_t)(gb + (idx >> 8)) * Hn + (idx & 255)];
        __syncthreads();
        unsigned long long acc = 0;
        const ulonglong2* ev = (const ulonglong2*)&embt[gl * 260];
        const ulonglong2* wv = (const ulonglong2*)&wih[rl * 260];
        #pragma unroll 8
        for (int k4 = 0; k4 < 64; k4++) {
            const ulonglong2 e = ev[k4], w = wv[k4];
            acc = ffma2(e.x, w.x, acc);
            acc = ffma2(e.y, w.y, acc);
        }
        g_ihpre[(size_t)(gb + gl) * 1024 + j0 + rl] = hsum2(acc) + bs[rl];
        __syncthreads();
    }
}

// =====================================================================
// K3: LSTM as ONE cluster of 8 CTAs (DSMEM h-broadcast, cluster.sync/step).
// CTA r owns hidden units [32r, 32r+32); thread (b, hu) keeps c in a reg.
// =====================================================================
__global__ __launch_bounds__(512) __cluster_dims__(8, 1, 1)
void k_lstm(const float* __restrict__ W_hh, const float* __restrict__ cls_W,
            const float* __restrict__ cls_b, float* __restrict__ out)
{
    extern __shared__ float s[];
    float* Ws  = s;                 // 128 x 260 = 33280
    float* hsb = s + 33280;         // 2 x 16 x 260 = 8320
    // total 41600 floats = 166400 B

    const int tid = threadIdx.x;
    uint32_t rank;
    asm("mov.u32 %0, %%cluster_ctarank;" : "=r"(rank));

    const int b  = tid & 15;        // batch
    const int qg = tid >> 4;        // 0..31 local hidden unit
    const int hug = (int)rank * 32 + qg;

    // W_hh slice: row q = qg*4+gate -> global row j = gate*256 + rank*32 + qg
    for (int idx = tid; idx < 128 * 256; idx += 512) {
        const int q = idx >> 8, k = idx & 255;
        const int j = (q & 3) * Hn + (int)rank * 32 + (q >> 2);
        Ws[q * 260 + k] = W_hh[(size_t)j * Hn + k];
    }
    for (int i = tid; i < 2 * 16 * 260; i += 512) hsb[i] = 0.f;
    __syncthreads();
    CLUSTER_SYNC_();

    const ulonglong2* w0 = (const ulonglong2*)&Ws[(qg * 4 + 0) * 260];
    const ulonglong2* w1 = (const ulonglong2*)&Ws[(qg * 4 + 1) * 260];
    const ulonglong2* w2 = (const ulonglong2*)&Ws[(qg * 4 + 2) * 260];
    const ulonglong2* w3 = (const ulonglong2*)&Ws[(qg * 4 + 3) * 260];

    float cc = 0.f;
    float hn = 0.f;
    for (int t = 0; t < Tn; t++) {
        const size_t gbase = (size_t)(t * Bn + b) * 1024;
        const float ih0 = __ldcg(&g_ihpre[gbase + 0 * Hn + hug]);
        const float ih1 = __ldcg(&g_ihpre[gbase + 1 * Hn + hug]);
        const float ih2 = __ldcg(&g_ihpre[gbase + 2 * Hn + hug]);
        const float ih3 = __ldcg(&g_ihpre[gbase + 3 * Hn + hug]);

        const ulonglong2* hv = (const ulonglong2*)&hsb[(t & 1) * 4160 + b * 260];
        unsigned long long a0 = 0, a1 = 0, a2 = 0, a3 = 0;
        #pragma unroll 8
        for (int k4 = 0; k4 < 64; k4++) {
            const ulonglong2 h2 = hv[k4];
            const ulonglong2 x0 = w0[k4], x1 = w1[k4], x2 = w2[k4], x3 = w3[k4];
            a0 = ffma2(h2.x, x0.x, a0); a0 = ffma2(h2.y, x0.y, a0);
            a1 = ffma2(h2.x, x1.x, a1); a1 = ffma2(h2.y, x1.y, a1);
            a2 = ffma2(h2.x, x2.x, a2); a2 = ffma2(h2.y, x2.y, a2);
            a3 = ffma2(h2.x, x3.x, a3); a3 = ffma2(h2.y, x3.y, a3);
        }
        const float gi = hsum2(a0) + ih0;
        const float gf = hsum2(a1) + ih1;
        const float gg = hsum2(a2) + ih2;
        const float go = hsum2(a3) + ih3;
        cc = sigmoidf_(gf) * cc + sigmoidf_(gi) * tanhf(gg);
        hn = sigmoidf_(go) * tanhf(cc);

        // push h(b, hug) to all 8 CTAs' next buffer
        const uint32_t laddr = smem_u32(&hsb[((t + 1) & 1) * 4160 + b * 260 + hug]);
        #pragma unroll
        for (int dr = 0; dr < 8; dr++) {
            uint32_t ra;
            asm("mapa.shared::cluster.u32 %0, %1, %2;" : "=r"(ra) : "r"(laddr), "r"(dr));
            asm volatile("st.shared::cluster.f32 [%0], %1;" :: "r"(ra), "f"(hn) : "memory");
        }
        CLUSTER_SYNC_();
    }

    // final h (step 16) lives in hsb buffer 0 of EVERY CTA; rank 0 classifies
    if (rank == 0) {
        const int wb = tid >> 5, lane = tid & 31;   // warp wb handles batch wb
        const float* hr = &hsb[0 * 4160 + wb * 260];
        float p = 0.f;
        #pragma unroll 8
        for (int k = lane; k < Hn; k += 32) p += hr[k] * __ldg(&cls_W[k]);
        #pragma unroll
        for (int o = 16; o; o >>= 1) p += __shfl_xor_sync(0xFFFFFFFFu, p, o);
        if (lane == 0) out[wb] = p + cls_b[0];
    }
    CLUSTER_SYNC_();
}

// =====================================================================
extern "C" void kernel_launch(void* const* d_in, const int* in_sizes, int n_in,
                              void* d_out, int out_size)
{
    (void)in_sizes; (void)n_in; (void)out_size;
    const float* x     = (const float*)d_in[0];
    const int*   ei    = (const int*)  d_in[1];
    const float* W1    = (const float*)d_in[2];
    const float* b1    = (const float*)d_in[3];
    const float* Wl    = (const float*)d_in[4];
    const float* Wr    = (const float*)d_in[5];
    const float* sb    = (const float*)d_in[6];
    const float* W2    = (const float*)d_in[7];
    const float* b2    = (const float*)d_in[8];
    const float* W_ih  = (const float*)d_in[9];
    const float* W_hh  = (const float*)d_in[10];
    const float* b_ih  = (const float*)d_in[11];
    const float* b_hh  = (const float*)d_in[12];
    const float* cls_W = (const float*)d_in[13];
    const float* cls_b = (const float*)d_in[14];
    float* out = (float*)d_out;

    const size_t smem1 = 55620 * sizeof(float);  // 222480 B
    const size_t smem3 = 41600 * sizeof(float);  // 166400 B
    cudaFuncSetAttribute(k_embed, cudaFuncAttributeMaxDynamicSharedMemorySize, (int)smem1);
    cudaFuncSetAttribute(k_lstm,  cudaFuncAttributeMaxDynamicSharedMemorySize, (int)smem3);

    k_embed<<<NG, NT, smem1>>>(x, ei, W1, b1, Wl, Wr, sb, W2, b2);
    k_prep <<<64, 256>>>(W_ih, b_ih, b_hh);
    k_lstm <<<8, 512, smem3>>>(W_hh, cls_W, cls_b, out);
}

// round 7
// speedup vs baseline: 1.1669x; 1.0047x over previous
#include <cuda_runtime.h>
#include <cstdint>

#define NT 512
constexpr int Tn  = 16;
constexpr int Bn  = 16;
constexpr int Nn  = 1024;
constexpr int En  = 16384;
constexpr int Fin = 128;
constexpr int Hn  = 256;
constexpr int Kn  = 820;
constexpr int NG  = Tn * Bn;   // 256 graphs

// ---------------- global scratch ----------------
__device__ float g_emb[NG * Hn];
__device__ float g_ihpre[NG * 4 * Hn];   // [g][j], j = gate*256 + hu

__device__ __forceinline__ float sigmoidf_(float v) { return 1.0f / (1.0f + expf(-v)); }

// ---------------- f32x2 helpers ----------------
__device__ __forceinline__ unsigned long long pk2(float a, float b) {
    unsigned long long r; asm("mov.b64 %0,{%1,%2};" : "=l"(r) : "f"(a), "f"(b)); return r;
}
__device__ __forceinline__ float2 upk(unsigned long long v) {
    float2 o; asm("mov.b64 {%0,%1},%2;" : "=f"(o.x), "=f"(o.y) : "l"(v)); return o;
}
__device__ __forceinline__ unsigned long long ffma2(unsigned long long a, unsigned long long b, unsigned long long c) {
    unsigned long long d; asm("fma.rn.f32x2 %0,%1,%2,%3;" : "=l"(d) : "l"(a), "l"(b), "l"(c)); return d;
}
__device__ __forceinline__ float hsum2(unsigned long long v) { float2 o = upk(v); return o.x + o.y; }

__device__ __forceinline__ uint32_t smem_u32(const void* p) {
    uint32_t a;
    asm("{ .reg .u64 t; cvta.to.shared.u64 t, %1; cvt.u32.u64 %0, t; }" : "=r"(a) : "l"(p));
    return a;
}

#define CLUSTER_SYNC_() do { \
    asm volatile("barrier.cluster.arrive.aligned;" ::: "memory"); \
    asm volatile("barrier.cluster.wait.aligned;" ::: "memory"); \
} while (0)

// conv1 half (f32x2): 256 threads (gt in [0,256)), nodes [pb, pb+512)
// w1p: u64 array [f2][c] = {W1[2f2][c], W1[2f2+1][c]}
__device__ __forceinline__ void conv1_half(const float* __restrict__ xg,
                                           const unsigned long long* w1p,
                                           float* A, int gt, int pb)
{
    const int mq = gt & 3;
    const int nb = gt >> 2;
    const int c0 = mq * 4;
    for (int n = pb + nb; n < pb + 512; n += 64) {
        unsigned long long a0 = 0, a1 = 0, a2 = 0, a3 = 0;
        const ulonglong2* xr = (const ulonglong2*)(xg + (size_t)n * Fin);
        #pragma unroll 8
        for (int i = 0; i < 32; i++) {
            const ulonglong2 xv = xr[i];   // xv.x: f={4i,4i+1}; xv.y: f={4i+2,4i+3}
            const ulonglong2* wp = (const ulonglong2*)&w1p[(2 * i) * 16 + c0];
            const ulonglong2* wq = (const ulonglong2*)&w1p[(2 * i + 1) * 16 + c0];
            const ulonglong2 wa = wp[0], wb = wp[1];
            const ulonglong2 wc = wq[0], wd = wq[1];
            a0 = ffma2(xv.x, wa.x, a0); a1 = ffma2(xv.x, wa.y, a1);
            a2 = ffma2(xv.x, wb.x, a2); a3 = ffma2(xv.x, wb.y, a3);
            a0 = ffma2(xv.y, wc.x, a0); a1 = ffma2(xv.y, wc.y, a1);
            a2 = ffma2(xv.y, wd.x, a2); a3 = ffma2(xv.y, wd.y, a3);
        }
        *(float4*)&A[n * 16 + c0] = make_float4(hsum2(a0), hsum2(a1), hsum2(a2), hsum2(a3));
    }
}

// =====================================================================
// K1: per-graph embedding. One CTA per graph. (R6-verified structure)
// =====================================================================
__global__ __launch_bounds__(NT) void k_embed(
    const float* __restrict__ x, const int* __restrict__ ei,
    const float* __restrict__ W1, const float* __restrict__ b1,
    const float* __restrict__ Wl, const float* __restrict__ Wr,
    const float* __restrict__ sb,
    const float* __restrict__ W2, const float* __restrict__ b2)
{
    extern __shared__ float sm[];
    float*              A      = sm;                                 // [0,16384)
    float*              Bf     = sm + 16384;                         // [16384,32768)
    unsigned long long* keys   = (unsigned long long*)(sm + 32768);  // 1024 u64
    unsigned short*     srcs   = (unsigned short*)(sm + 34816);      // 16384 u16
    int*                off    = (int*)(sm + 43008);                 // 1028
    int*                cur    = (int*)(sm + 44036);                 // 1024
    float*              pv     = sm + 45060;                         // 1024
    float*              score  = sm + 46084;                         // 1024
    int*                newidx = (int*)(sm + 47108);                 // 1024
    float*              dinv2  = sm + 48132;                         // 1024
    unsigned long long* w1p    = (unsigned long long*)(sm + 49156);  // 1024 u64 (= 2048 floats)
    float*              w2s    = sm + 51204;                         // 4096 (aliases tmppos)
    unsigned char*      tmppos = (unsigned char*)(sm + 51204);       // 16384 u8
    float*              b2s    = sm + 55300;                         // 256
    float*              cst    = sm + 55556;                         // 64
    // total 55620 floats = 222480 B

    const int tid = threadIdx.x;
    const int g   = blockIdx.x;
    const float* xg   = x  + (size_t)g * Nn * Fin;
    const int*   srcp = ei + (size_t)g * 2 * En;
    const int*   dstp = srcp + En;

    for (int i = tid; i < 1024; i += NT) {
        const int f2 = i >> 4, c = i & 15;
        w1p[i] = pk2(W1[(2 * f2) * 16 + c], W1[(2 * f2 + 1) * 16 + c]);
    }
    if (tid < 16) { cst[tid] = b1[tid]; cst[16 + tid] = Wl[tid]; cst[32 + tid] = Wr[tid]; }
    if (tid == 0) cst[48] = sb[0];
    for (int i = tid; i < Nn; i += NT) cur[i] = 0;
    __syncthreads();

    // --- phase A: warps 0-7 conv1 nodes [0,512) || warps 8-15 histogram+rank
    if (tid < 256) {
        conv1_half(xg, w1p, A, tid, 0);
    } else {
        for (int e = tid - 256; e < En; e += 256)
            tmppos[e] = (unsigned char)atomicAdd(&cur[dstp[e]], 1);
    }
    __syncthreads();

    // --- exclusive Blelloch scan of counts -> off[0..1024] ------------------
    for (int i = tid; i < Nn; i += NT) off[i] = cur[i];
    for (int d2 = 1; d2 < Nn; d2 <<= 1) {
        __syncthreads();
        const int idx = (tid + 1) * (d2 << 1) - 1;
        if (idx < Nn) off[idx] += off[idx - d2];
    }
    __syncthreads();
    if (tid == 0) { off[Nn] = off[Nn - 1]; off[Nn - 1] = 0; }
    for (int d2 = Nn >> 1; d2 >= 1; d2 >>= 1) {
        __syncthreads();
        const int idx = (tid + 1) * (d2 << 1) - 1;
        if (idx < Nn) { const int t = off[idx - d2]; off[idx - d2] = off[idx]; off[idx] += t; }
    }
    __syncthreads();
    for (int i = tid; i < Nn; i += NT)
        pv[i] = rsqrtf(1.0f + (float)(off[i + 1] - off[i]));   // dinv
    __syncthreads();

    // --- phase C: warps 0-7 conv1 nodes [512,1024) || warps 8-15 placement --
    if (tid < 256) {
        conv1_half(xg, w1p, A, tid, 512);
    } else {
        for (int e = tid - 256; e < En; e += 256)
            srcs[off[dstp[e]] + tmppos[e]] = (unsigned short)srcp[e];
    }
    __syncthreads();

    // tmppos dead -> load W2/b2 into its alias; pre-scale A rows by dinv
    for (int i = tid; i < 16 * Hn; i += NT) w2s[i] = W2[i];
    for (int i = tid; i < Hn; i += NT) b2s[i] = b2[i];
    for (int i = tid; i < Nn * 16; i += NT) A[i] *= pv[i >> 4];
    __syncthreads();

    // --- conv1 gather (pure sum, self included) + bias + relu -> Bf = h1 ----
    {
        const int grp = tid >> 2, q = tid & 3;
        const float bx = cst[q * 4 + 0], by = cst[q * 4 + 1];
        const float bz = cst[q * 4 + 2], bw = cst[q * 4 + 3];
        for (int d = grp; d < Nn; d += 128) {
            const int e0 = off[d], e1 = off[d + 1];
            float4 ac = *(const float4*)&A[d * 16 + q * 4];   // self (scaled)
            for (int j = e0; j < e1; j++) {
                const float4 v = *(const float4*)&A[srcs[j] * 16 + q * 4];
                ac.x += v.x; ac.y += v.y; ac.z += v.z; ac.w += v.w;
            }
            const float dd = pv[d];
            float4 o;
            o.x = fmaxf(fmaf(ac.x, dd, bx), 0.f);
            o.y = fmaxf(fmaf(ac.y, dd, by), 0.f);
            o.z = fmaxf(fmaf(ac.z, dd, bz), 0.f);
            o.w = fmaxf(fmaf(ac.w, dd, bw), 0.f);
            *(float4*)&Bf[d * 16 + q * 4] = o;
        }
    }
    __syncthreads();

    // --- p[n] = h1[n].Wl ; score[n] = h1[n].Wr + sag_b ----------------------
    for (int n = tid; n < Nn; n += NT) {
        float pl = 0.f, pr = cst[48];
        #pragma unroll
        for (int m = 0; m < 16; m++) {
            const float h = Bf[n * 16 + m];
            pl = fmaf(h, cst[16 + m], pl);
            pr = fmaf(h, cst[32 + m], pr);
        }
        pv[n] = pl; score[n] = pr;
    }
    __syncthreads();

    // --- score[d] += sum p[srcs] ; sortable keys ------------------------------
    for (int d = tid; d < Nn; d += NT) {
        float s = score[d];
        const int e0 = off[d], e1 = off[d + 1];
        for (int j = e0; j < e1; j++) s += pv[srcs[j]];
        score[d] = s;
        unsigned u = __float_as_uint(s);
        u = (u & 0x80000000u) ? ~u : (u | 0x80000000u);
        keys[d] = ((unsigned long long)(~u) << 32) | (unsigned)d;
    }
    __syncthreads();

    // --- bitonic sort ----------------------------------------------------------
    for (int k = 2; k <= Nn; k <<= 1) {
        for (int j = k >> 1; j > 0; j >>= 1) {
            const int lo = ((tid & ~(j - 1)) << 1) | (tid & (j - 1));
            const int hi = lo + j;
            const unsigned long long a = keys[lo], b = keys[hi];
            const bool up = ((lo & k) == 0);
            if (up ? (a > b) : (a < b)) { keys[lo] = b; keys[hi] = a; }
            __syncthreads();
        }
    }

    // --- newidx + gate -----------------------------------------------------------
    for (int n = tid; n < Nn; n += NT) newidx[n] = -1;
    __syncthreads();
    float* tvf = (float*)cur;
    for (int r = tid; r < Kn; r += NT) {
        const int n = (int)(keys[r] & 0xFFFFFFFFull);
        newidx[n] = r;
        tvf[r] = tanhf(score[n]);
    }
    __syncthreads();
    for (int i = tid; i < Kn * 16; i += NT) {
        const int r = i >> 4, m = i & 15;
        const int n = (int)(keys[r] & 0xFFFFFFFFull);
        A[r * 16 + m] = Bf[n * 16 + m] * tvf[r];
    }
    __syncthreads();

    // --- deg2 over valid remapped edges -----------------------------------------
    for (int d = tid; d < Nn; d += NT) {
        const int nd = newidx[d];
        if (nd >= 0) {
            int c = 0;
            const int e0 = off[d], e1 = off[d + 1];
            for (int j = e0; j < e1; j++) c += (newidx[srcs[j]] >= 0);
            dinv2[nd] = rsqrtf(1.0f + (float)c);
        }
    }
    __syncthreads();
    for (int i = tid; i < Kn * 16; i += NT) A[i] *= dinv2[i >> 4];   // pre-scale xp
    __syncthreads();

    // --- conv2 pre-aggregation (MID space) -> Bf rows [0,K) ----------------------
    {
        const int grp = tid >> 2, q = tid & 3;
        for (int d = grp; d < Nn; d += 128) {
            const int nd = newidx[d];
            if (nd < 0) continue;
            const int e0 = off[d], e1 = off[d + 1];
            float4 ac = *(const float4*)&A[nd * 16 + q * 4];   // self (scaled)
            for (int j = e0; j < e1; j++) {
                const int ns = newidx[srcs[j]];
                if (ns >= 0) {
                    const float4 v = *(const float4*)&A[ns * 16 + q * 4];
                    ac.x += v.x; ac.y += v.y; ac.z += v.z; ac.w += v.w;
                }
            }
            const float dd = dinv2[nd];
            *(float4*)&Bf[nd * 16 + q * 4] = make_float4(ac.x * dd, ac.y * dd, ac.z * dd, ac.w * dd);
        }
    }
    __syncthreads();

    // --- h2 = relu(pre @ W2 + b2), mean over K -> g_emb (f32x2, regs) ------------
    {
        const int cg = tid & 63, rb = tid >> 6;
        const int c0 = cg * 4;
        unsigned long long wreg[32];
        #pragma unroll
        for (int i = 0; i < 4; i++)
            #pragma unroll
            for (int k2 = 0; k2 < 8; k2++)
                wreg[i * 8 + k2] = pk2(w2s[(2 * k2) * Hn + c0 + i], w2s[(2 * k2 + 1) * Hn + c0 + i]);
        float biasv[4], accs[4];
        #pragma unroll
        for (int i = 0; i < 4; i++) { biasv[i] = b2s[c0 + i]; accs[i] = 0.f; }

        for (int r = rb; r < Kn; r += 8) {
            const ulonglong2* pr = (const ulonglong2*)&Bf[r * 16];
            const ulonglong2 v0 = pr[0], v1 = pr[1], v2 = pr[2], v3 = pr[3];
            #pragma unroll
            for (int i = 0; i < 4; i++) {
                unsigned long long dd_ = 0;
                dd_ = ffma2(v0.x, wreg[i * 8 + 0], dd_);
                dd_ = ffma2(v0.y, wreg[i * 8 + 1], dd_);
                dd_ = ffma2(v1.x, wreg[i * 8 + 2], dd_);
                dd_ = ffma2(v1.y, wreg[i * 8 + 3], dd_);
                dd_ = ffma2(v2.x, wreg[i * 8 + 4], dd_);
                dd_ = ffma2(v2.y, wreg[i * 8 + 5], dd_);
                dd_ = ffma2(v3.x, wreg[i * 8 + 6], dd_);
                dd_ = ffma2(v3.y, wreg[i * 8 + 7], dd_);
                accs[i] += fmaxf(hsum2(dd_) + biasv[i], 0.f);
            }
        }
        float* redf = (float*)keys;   // keys dead
        #pragma unroll
        for (int i = 0; i < 4; i++) redf[rb * 256 + c0 + i] = accs[i];
        __syncthreads();
        if (tid < 256) {
            float s = 0.f;
            #pragma unroll
            for (int rbi = 0; rbi < 8; rbi++) s += redf[rbi * 256 + tid];
            g_emb[(size_t)g * Hn + tid] = s * (1.0f / (float)Kn);
        }
    }
}

// =====================================================================
// K2: ihpre[g][j] = emb[g].W_ih[j] + b_ih[j] + b_hh[j]; 64 CTAs x 16 rows
// =====================================================================
__global__ __launch_bounds__(256) void k_prep(
    const float* __restrict__ W_ih, const float* __restrict__ b_ih,
    const float* __restrict__ b_hh)
{
    __shared__ float wih[16 * 260];
    __shared__ float embt[16 * 260];
    __shared__ float bs[16];
    const int tid = threadIdx.x;
    const int j0  = blockIdx.x * 16;

    for (int idx = tid; idx < 16 * 256; idx += 256)
        wih[(idx >> 8) * 260 + (idx & 255)] = W_ih[(size_t)(j0 + (idx >> 8)) * Hn + (idx & 255)];
    if (tid < 16) bs[tid] = b_ih[j0 + tid] + b_hh[j0 + tid];
    __syncthreads();

    const int rl = tid & 15, gl = tid >> 4;
    for (int tile = 0; tile < 16; tile++) {
        const int gb = tile * 16;
        for (int idx = tid; idx < 16 * 256; idx += 256)
            embt[(idx >> 8) * 260 + (idx & 255)] = g_emb[(size_t)(gb + (idx >> 8)) * Hn + (idx & 255)];
        __syncthreads();
        unsigned long long acc = 0;
        const ulonglong2* ev = (const ulonglong2*)&embt[gl * 260];
        const ulonglong2* wv = (const ulonglong2*)&wih[rl * 260];
        #pragma unroll 8
        for (int k4 = 0; k4 < 64; k4++) {
            const ulonglong2 e = ev[k4], w = wv[k4];
            acc = ffma2(e.x, w.x, acc);
            acc = ffma2(e.y, w.y, acc);
        }
        g_ihpre[(size_t)(gb + gl) * 1024 + j0 + rl] = hsum2(acc) + bs[rl];
        __syncthreads();
    }
}

// =====================================================================
// K3: LSTM, one 8-CTA cluster. W_hh in REGISTERS (step-invariant).
// Thread (jp, kc): rows {2jp, 2jp+1} of CTA's 128 j-rows, k in [32kc,32kc+32).
// h in smem with 36-float chunk padding (conflict-free across kc lanes).
// =====================================================================
__global__ __launch_bounds__(512) __cluster_dims__(8, 1, 1)
void k_lstm(const float* __restrict__ W_hh, const float* __restrict__ cls_W,
            const float* __restrict__ cls_b, float* __restrict__ out)
{
    extern __shared__ float s[];
    float* hsb = s;            // 2 * 16 * 288 = 9216   [buf][b][kc*36 + idx]
    float* gdm = s + 9216;     // 128 * 17 = 2176       [q][b]
    float* iht = s + 11392;    // 32768                 [(t*16+b)*32 + hu_l][4]
    // total 44160 floats = 176640 B

    const int tid = threadIdx.x;
    uint32_t rank; asm("mov.u32 %0, %%cluster_ctarank;" : "=r"(rank));
    const int kc = tid & 7;
    const int jp = tid >> 3;        // 0..63

    // --- step-invariant weights into registers -------------------------------
    unsigned long long wA[16], wB[16];
    {
        const int q0 = 2 * jp, q1 = 2 * jp + 1;
        const float* r0 = W_hh + (size_t)((q0 & 3) * 256 + (int)rank * 32 + (q0 >> 2)) * 256 + kc * 32;
        const float* r1 = W_hh + (size_t)((q1 & 3) * 256 + (int)rank * 32 + (q1 >> 2)) * 256 + kc * 32;
        #pragma unroll
        for (int i = 0; i < 16; i++) {
            wA[i] = pk2(r0[2 * i], r0[2 * i + 1]);
            wB[i] = pk2(r1[2 * i], r1[2 * i + 1]);
        }
    }
    // --- stage this CTA's ihpre slice: [tb 256][g 4][hl 32] -> [tb][hl][g] ----
    for (int idx = tid; idx < 32768; idx += 512) {
        const int tb = idx >> 7, gq = (idx >> 5) & 3, hl = idx & 31;
        iht[(tb * 32 + hl) * 4 + gq] =
            g_ihpre[(size_t)tb * 1024 + gq * 256 + (int)rank * 32 + hl];
    }
    for (int i = tid; i < 2 * 16 * 288; i += 512) hsb[i] = 0.f;
    __syncthreads();
    CLUSTER_SYNC_();

    const int eb = tid & 15, eh = tid >> 4;   // epilogue role: batch, local hu
    float creg = 0.f;

    for (int t = 0; t < Tn; t++) {
        const float* hb = &hsb[(t & 1) * 4608];
        #pragma unroll
        for (int half = 0; half < 2; half++) {
            unsigned long long aA[8], aB[8];
            #pragma unroll
            for (int i = 0; i < 8; i++) { aA[i] = 0ull; aB[i] = 0ull; }
            #pragma unroll
            for (int b8 = 0; b8 < 8; b8++) {
                const int b = half * 8 + b8;
                const ulonglong2* hv = (const ulonglong2*)&hb[b * 288 + kc * 36];
                #pragma unroll
                for (int i2 = 0; i2 < 8; i2++) {
                    const ulonglong2 h2 = hv[i2];
                    aA[b8] = ffma2(h2.x, wA[2 * i2],     aA[b8]);
                    aA[b8] = ffma2(h2.y, wA[2 * i2 + 1], aA[b8]);
                    aB[b8] = ffma2(h2.x, wB[2 * i2],     aB[b8]);
                    aB[b8] = ffma2(h2.y, wB[2 * i2 + 1], aB[b8]);
                }
            }
            #pragma unroll
            for (int b8 = 0; b8 < 8; b8++) {
                float fA = hsum2(aA[b8]);
                float fB = hsum2(aB[b8]);
                fA += __shfl_xor_sync(0xFFFFFFFFu, fA, 1);
                fA += __shfl_xor_sync(0xFFFFFFFFu, fA, 2);
                fA += __shfl_xor_sync(0xFFFFFFFFu, fA, 4);
                fB += __shfl_xor_sync(0xFFFFFFFFu, fB, 1);
                fB += __shfl_xor_sync(0xFFFFFFFFu, fB, 2);
                fB += __shfl_xor_sync(0xFFFFFFFFu, fB, 4);
                if (kc == 0) {
                    gdm[(2 * jp) * 17 + half * 8 + b8]     = fA;
                    gdm[(2 * jp + 1) * 17 + half * 8 + b8] = fB;
                }
            }
        }
        __syncthreads();

        // --- epilogue: thread (eb, eh) computes c,h for hidden unit rank*32+eh
        {
            const float4 ihv = *(const float4*)&iht[((t * 16 + eb) * 32 + eh) * 4];
            const int q0 = eh * 4;
            const float gi = gdm[(q0 + 0) * 17 + eb] + ihv.x;
            const float gf = gdm[(q0 + 1) * 17 + eb] + ihv.y;
            const float gg = gdm[(q0 + 2) * 17 + eb] + ihv.z;
            const float go = gdm[(q0 + 3) * 17 + eb] + ihv.w;
            creg = sigmoidf_(gf) * creg + sigmoidf_(gi) * tanhf(gg);
            const float hn = sigmoidf_(go) * tanhf(creg);
            const uint32_t laddr =
                smem_u32(&hsb[((t + 1) & 1) * 4608 + eb * 288 + (int)rank * 36 + eh]);
            #pragma unroll
            for (int dr = 0; dr < 8; dr++) {
                uint32_t ra;
                asm("mapa.shared::cluster.u32 %0, %1, %2;" : "=r"(ra) : "r"(laddr), "r"(dr));
                asm volatile("st.shared::cluster.f32 [%0], %1;" :: "r"(ra), "f"(hn) : "memory");
            }
        }
        CLUSTER_SYNC_();
    }

    // final h (step 16) in hsb buffer 0 of every CTA; rank 0 classifies
    if (rank == 0) {
        const int wb = tid >> 5, lane = tid & 31;
        float p = 0.f;
        #pragma unroll
        for (int i = 0; i < 8; i++) {
            const int k = i * 32 + lane;
            p += hsb[wb * 288 + i * 36 + lane] * __ldg(&cls_W[k]);
        }
        #pragma unroll
        for (int o = 16; o; o >>= 1) p += __shfl_xor_sync(0xFFFFFFFFu, p, o);
        if (lane == 0) out[wb] = p + cls_b[0];
    }
    CLUSTER_SYNC_();
}

// =====================================================================
extern "C" void kernel_launch(void* const* d_in, const int* in_sizes, int n_in,
                              void* d_out, int out_size)
{
    (void)in_sizes; (void)n_in; (void)out_size;
    const float* x     = (const float*)d_in[0];
    const int*   ei    = (const int*)  d_in[1];
    const float* W1    = (const float*)d_in[2];
    const float* b1    = (const float*)d_in[3];
    const float* Wl    = (const float*)d_in[4];
    const float* Wr    = (const float*)d_in[5];
    const float* sb    = (const float*)d_in[6];
    const float* W2    = (const float*)d_in[7];
    const float* b2    = (const float*)d_in[8];
    const float* W_ih  = (const float*)d_in[9];
    const float* W_hh  = (const float*)d_in[10];
    const float* b_ih  = (const float*)d_in[11];
    const float* b_hh  = (const float*)d_in[12];
    const float* cls_W = (const float*)d_in[13];
    const float* cls_b = (const float*)d_in[14];
    float* out = (float*)d_out;

    const size_t smem1 = 55620 * sizeof(float);  // 222480 B
    const size_t smem3 = 44160 * sizeof(float);  // 176640 B
    cudaFuncSetAttribute(k_embed, cudaFuncAttributeMaxDynamicSharedMemorySize, (int)smem1);
    cudaFuncSetAttribute(k_lstm,  cudaFuncAttributeMaxDynamicSharedMemorySize, (int)smem3);

    k_embed<<<NG, NT, smem1>>>(x, ei, W1, b1, Wl, Wr, sb, W2, b2);
    k_prep <<<64, 256>>>(W_ih, b_ih, b_hh);
    k_lstm <<<8, 512, smem3>>>(W_hh, cls_W, cls_b, out);
}

// round 8
// speedup vs baseline: 1.2382x; 1.0611x over previous
#include <cuda_runtime.h>
#include <cstdint>

#define NT 512
constexpr int Tn  = 16;
constexpr int Bn  = 16;
constexpr int Nn  = 1024;
constexpr int En  = 16384;
constexpr int Fin = 128;
constexpr int Hn  = 256;
constexpr int Kn  = 820;
constexpr int NG  = Tn * Bn;   // 256 graphs

// ---------------- global scratch ----------------
__device__ float g_emb[NG * Hn];

__device__ __forceinline__ float sigmoidf_(float v) { return 1.0f / (1.0f + expf(-v)); }

// ---------------- f32x2 helpers ----------------
__device__ __forceinline__ unsigned long long pk2(float a, float b) {
    unsigned long long r; asm("mov.b64 %0,{%1,%2};" : "=l"(r) : "f"(a), "f"(b)); return r;
}
__device__ __forceinline__ float2 upk(unsigned long long v) {
    float2 o; asm("mov.b64 {%0,%1},%2;" : "=f"(o.x), "=f"(o.y) : "l"(v)); return o;
}
__device__ __forceinline__ unsigned long long ffma2(unsigned long long a, unsigned long long b, unsigned long long c) {
    unsigned long long d; asm("fma.rn.f32x2 %0,%1,%2,%3;" : "=l"(d) : "l"(a), "l"(b), "l"(c)); return d;
}
__device__ __forceinline__ float hsum2(unsigned long long v) { float2 o = upk(v); return o.x + o.y; }

__device__ __forceinline__ uint32_t smem_u32(const void* p) {
    uint32_t a;
    asm("{ .reg .u64 t; cvta.to.shared.u64 t, %1; cvt.u32.u64 %0, t; }" : "=r"(a) : "l"(p));
    return a;
}

#define CLUSTER_SYNC_() do { \
    asm volatile("barrier.cluster.arrive.aligned;" ::: "memory"); \
    asm volatile("barrier.cluster.wait.aligned;" ::: "memory"); \
} while (0)

// conv1 half (f32x2): 256 threads (gt in [0,256)), nodes [pb, pb+512)
__device__ __forceinline__ void conv1_half(const float* __restrict__ xg,
                                           const unsigned long long* w1p,
                                           float* A, int gt, int pb)
{
    const int mq = gt & 3;
    const int nb = gt >> 2;
    const int c0 = mq * 4;
    for (int n = pb + nb; n < pb + 512; n += 64) {
        unsigned long long a0 = 0, a1 = 0, a2 = 0, a3 = 0;
        const ulonglong2* xr = (const ulonglong2*)(xg + (size_t)n * Fin);
        #pragma unroll 8
        for (int i = 0; i < 32; i++) {
            const ulonglong2 xv = xr[i];
            const ulonglong2* wp = (const ulonglong2*)&w1p[(2 * i) * 16 + c0];
            const ulonglong2* wq = (const ulonglong2*)&w1p[(2 * i + 1) * 16 + c0];
            const ulonglong2 wa = wp[0], wb = wp[1];
            const ulonglong2 wc = wq[0], wd = wq[1];
            a0 = ffma2(xv.x, wa.x, a0); a1 = ffma2(xv.x, wa.y, a1);
            a2 = ffma2(xv.x, wb.x, a2); a3 = ffma2(xv.x, wb.y, a3);
            a0 = ffma2(xv.y, wc.x, a0); a1 = ffma2(xv.y, wc.y, a1);
            a2 = ffma2(xv.y, wd.x, a2); a3 = ffma2(xv.y, wd.y, a3);
        }
        *(float4*)&A[n * 16 + c0] = make_float4(hsum2(a0), hsum2(a1), hsum2(a2), hsum2(a3));
    }
}

// =====================================================================
// K1: per-graph embedding. One CTA per graph. (verified R7 body)
// =====================================================================
__global__ __launch_bounds__(NT) void k_embed(
    const float* __restrict__ x, const int* __restrict__ ei,
    const float* __restrict__ W1, const float* __restrict__ b1,
    const float* __restrict__ Wl, const float* __restrict__ Wr,
    const float* __restrict__ sb,
    const float* __restrict__ W2, const float* __restrict__ b2)
{
    extern __shared__ float sm[];
    float*              A      = sm;                                 // [0,16384)
    float*              Bf     = sm + 16384;                         // [16384,32768)
    unsigned long long* keys   = (unsigned long long*)(sm + 32768);  // 1024 u64
    unsigned short*     srcs   = (unsigned short*)(sm + 34816);      // 16384 u16
    int*                off    = (int*)(sm + 43008);                 // 1028
    int*                cur    = (int*)(sm + 44036);                 // 1024
    float*              pv     = sm + 45060;                         // 1024
    float*              score  = sm + 46084;                         // 1024
    int*                newidx = (int*)(sm + 47108);                 // 1024
    float*              dinv2  = sm + 48132;                         // 1024
    unsigned long long* w1p    = (unsigned long long*)(sm + 49156);  // 1024 u64
    float*              w2s    = sm + 51204;                         // 4096 (aliases tmppos)
    unsigned char*      tmppos = (unsigned char*)(sm + 51204);       // 16384 u8
    float*              b2s    = sm + 55300;                         // 256
    float*              cst    = sm + 55556;                         // 64
    // total 55620 floats = 222480 B

    const int tid = threadIdx.x;
    const int g   = blockIdx.x;
    const float* xg   = x  + (size_t)g * Nn * Fin;
    const int*   srcp = ei + (size_t)g * 2 * En;
    const int*   dstp = srcp + En;

    for (int i = tid; i < 1024; i += NT) {
        const int f2 = i >> 4, c = i & 15;
        w1p[i] = pk2(W1[(2 * f2) * 16 + c], W1[(2 * f2 + 1) * 16 + c]);
    }
    if (tid < 16) { cst[tid] = b1[tid]; cst[16 + tid] = Wl[tid]; cst[32 + tid] = Wr[tid]; }
    if (tid == 0) cst[48] = sb[0];
    for (int i = tid; i < Nn; i += NT) cur[i] = 0;
    __syncthreads();

    // --- phase A: warps 0-7 conv1 nodes [0,512) || warps 8-15 histogram+rank
    if (tid < 256) {
        conv1_half(xg, w1p, A, tid, 0);
    } else {
        for (int e = tid - 256; e < En; e += 256)
            tmppos[e] = (unsigned char)atomicAdd(&cur[dstp[e]], 1);
    }
    __syncthreads();

    // --- exclusive Blelloch scan of counts -> off[0..1024] ------------------
    for (int i = tid; i < Nn; i += NT) off[i] = cur[i];
    for (int d2 = 1; d2 < Nn; d2 <<= 1) {
        __syncthreads();
        const int idx = (tid + 1) * (d2 << 1) - 1;
        if (idx < Nn) off[idx] += off[idx - d2];
    }
    __syncthreads();
    if (tid == 0) { off[Nn] = off[Nn - 1]; off[Nn - 1] = 0; }
    for (int d2 = Nn >> 1; d2 >= 1; d2 >>= 1) {
        __syncthreads();
        const int idx = (tid + 1) * (d2 << 1) - 1;
        if (idx < Nn) { const int t = off[idx - d2]; off[idx - d2] = off[idx]; off[idx] += t; }
    }
    __syncthreads();
    for (int i = tid; i < Nn; i += NT)
        pv[i] = rsqrtf(1.0f + (float)(off[i + 1] - off[i]));   // dinv
    __syncthreads();

    // --- phase C: warps 0-7 conv1 nodes [512,1024) || warps 8-15 placement --
    if (tid < 256) {
        conv1_half(xg, w1p, A, tid, 512);
    } else {
        for (int e = tid - 256; e < En; e += 256)
            srcs[off[dstp[e]] + tmppos[e]] = (unsigned short)srcp[e];
    }
    __syncthreads();

    // tmppos dead -> load W2/b2 into its alias; pre-scale A rows by dinv
    for (int i = tid; i < 16 * Hn; i += NT) w2s[i] = W2[i];
    for (int i = tid; i < Hn; i += NT) b2s[i] = b2[i];
    for (int i = tid; i < Nn * 16; i += NT) A[i] *= pv[i >> 4];
    __syncthreads();

    // --- conv1 gather (pure sum, self included) + bias + relu -> Bf = h1 ----
    {
        const int grp = tid >> 2, q = tid & 3;
        const float bx = cst[q * 4 + 0], by = cst[q * 4 + 1];
        const float bz = cst[q * 4 + 2], bw = cst[q * 4 + 3];
        for (int d = grp; d < Nn; d += 128) {
            const int e0 = off[d], e1 = off[d + 1];
            float4 ac = *(const float4*)&A[d * 16 + q * 4];
            for (int j = e0; j < e1; j++) {
                const float4 v = *(const float4*)&A[srcs[j] * 16 + q * 4];
                ac.x += v.x; ac.y += v.y; ac.z += v.z; ac.w += v.w;
            }
            const float dd = pv[d];
            float4 o;
            o.x = fmaxf(fmaf(ac.x, dd, bx), 0.f);
            o.y = fmaxf(fmaf(ac.y, dd, by), 0.f);
            o.z = fmaxf(fmaf(ac.z, dd, bz), 0.f);
            o.w = fmaxf(fmaf(ac.w, dd, bw), 0.f);
            *(float4*)&Bf[d * 16 + q * 4] = o;
        }
    }
    __syncthreads();

    // --- p[n] = h1[n].Wl ; score[n] = h1[n].Wr + sag_b ----------------------
    for (int n = tid; n < Nn; n += NT) {
        float pl = 0.f, pr = cst[48];
        #pragma unroll
        for (int m = 0; m < 16; m++) {
            const float h = Bf[n * 16 + m];
            pl = fmaf(h, cst[16 + m], pl);
            pr = fmaf(h, cst[32 + m], pr);
        }
        pv[n] = pl; score[n] = pr;
    }
    __syncthreads();

    // --- score[d] += sum p[srcs] ; sortable keys ------------------------------
    for (int d = tid; d < Nn; d += NT) {
        float s = score[d];
        const int e0 = off[d], e1 = off[d + 1];
        for (int j = e0; j < e1; j++) s += pv[srcs[j]];
        score[d] = s;
        unsigned u = __float_as_uint(s);
        u = (u & 0x80000000u) ? ~u : (u | 0x80000000u);
        keys[d] = ((unsigned long long)(~u) << 32) | (unsigned)d;
    }
    __syncthreads();

    // --- bitonic sort ----------------------------------------------------------
    for (int k = 2; k <= Nn; k <<= 1) {
        for (int j = k >> 1; j > 0; j >>= 1) {
            const int lo = ((tid & ~(j - 1)) << 1) | (tid & (j - 1));
            const int hi = lo + j;
            const unsigned long long a = keys[lo], b = keys[hi];
            const bool up = ((lo & k) == 0);
            if (up ? (a > b) : (a < b)) { keys[lo] = b; keys[hi] = a; }
            __syncthreads();
        }
    }

    // --- newidx + gate -----------------------------------------------------------
    for (int n = tid; n < Nn; n += NT) newidx[n] = -1;
    __syncthreads();
    float* tvf = (float*)cur;
    for (int r = tid; r < Kn; r += NT) {
        const int n = (int)(keys[r] & 0xFFFFFFFFull);
        newidx[n] = r;
        tvf[r] = tanhf(score[n]);
    }
    __syncthreads();
    for (int i = tid; i < Kn * 16; i += NT) {
        const int r = i >> 4, m = i & 15;
        const int n = (int)(keys[r] & 0xFFFFFFFFull);
        A[r * 16 + m] = Bf[n * 16 + m] * tvf[r];
    }
    __syncthreads();

    // --- deg2 over valid remapped edges -----------------------------------------
    for (int d = tid; d < Nn; d += NT) {
        const int nd = newidx[d];
        if (nd >= 0) {
            int c = 0;
            const int e0 = off[d], e1 = off[d + 1];
            for (int j = e0; j < e1; j++) c += (newidx[srcs[j]] >= 0);
            dinv2[nd] = rsqrtf(1.0f + (float)c);
        }
    }
    __syncthreads();
    for (int i = tid; i < Kn * 16; i += NT) A[i] *= dinv2[i >> 4];
    __syncthreads();

    // --- conv2 pre-aggregation (MID space) -> Bf rows [0,K) ----------------------
    {
        const int grp = tid >> 2, q = tid & 3;
        for (int d = grp; d < Nn; d += 128) {
            const int nd = newidx[d];
            if (nd < 0) continue;
            const int e0 = off[d], e1 = off[d + 1];
            float4 ac = *(const float4*)&A[nd * 16 + q * 4];
            for (int j = e0; j < e1; j++) {
                const int ns = newidx[srcs[j]];
                if (ns >= 0) {
                    const float4 v = *(const float4*)&A[ns * 16 + q * 4];
                    ac.x += v.x; ac.y += v.y; ac.z += v.z; ac.w += v.w;
                }
            }
            const float dd = dinv2[nd];
            *(float4*)&Bf[nd * 16 + q * 4] = make_float4(ac.x * dd, ac.y * dd, ac.z * dd, ac.w * dd);
        }
    }
    __syncthreads();

    // --- h2 = relu(pre @ W2 + b2), mean over K -> g_emb (f32x2, regs) ------------
    {
        const int cg = tid & 63, rb = tid >> 6;
        const int c0 = cg * 4;
        unsigned long long wreg[32];
        #pragma unroll
        for (int i = 0; i < 4; i++)
            #pragma unroll
            for (int k2 = 0; k2 < 8; k2++)
                wreg[i * 8 + k2] = pk2(w2s[(2 * k2) * Hn + c0 + i], w2s[(2 * k2 + 1) * Hn + c0 + i]);
        float biasv[4], accs[4];
        #pragma unroll
        for (int i = 0; i < 4; i++) { biasv[i] = b2s[c0 + i]; accs[i] = 0.f; }

        for (int r = rb; r < Kn; r += 8) {
            const ulonglong2* pr = (const ulonglong2*)&Bf[r * 16];
            const ulonglong2 v0 = pr[0], v1 = pr[1], v2 = pr[2], v3 = pr[3];
            #pragma unroll
            for (int i = 0; i < 4; i++) {
                unsigned long long dd_ = 0;
                dd_ = ffma2(v0.x, wreg[i * 8 + 0], dd_);
                dd_ = ffma2(v0.y, wreg[i * 8 + 1], dd_);
                dd_ = ffma2(v1.x, wreg[i * 8 + 2], dd_);
                dd_ = ffma2(v1.y, wreg[i * 8 + 3], dd_);
                dd_ = ffma2(v2.x, wreg[i * 8 + 4], dd_);
                dd_ = ffma2(v2.y, wreg[i * 8 + 5], dd_);
                dd_ = ffma2(v3.x, wreg[i * 8 + 6], dd_);
                dd_ = ffma2(v3.y, wreg[i * 8 + 7], dd_);
                accs[i] += fmaxf(hsum2(dd_) + biasv[i], 0.f);
            }
        }
        float* redf = (float*)keys;
        #pragma unroll
        for (int i = 0; i < 4; i++) redf[rb * 256 + c0 + i] = accs[i];
        __syncthreads();
        if (tid < 256) {
            float s = 0.f;
            #pragma unroll
            for (int rbi = 0; rbi < 8; rbi++) s += redf[rbi * 256 + tid];
            g_emb[(size_t)g * Hn + tid] = s * (1.0f / (float)Kn);
        }
    }
}

// =====================================================================
// K2: LSTM, 16 clusters of 8 CTAs (one cluster per BATCH — independent).
// CTA (batch b, rank r) owns hidden units [32r,32r+32) = 128 gate rows.
// W_ih then W_hh rows live in the SAME registers (prologue reuse).
// h (256 floats) broadcast within cluster via DSMEM each step.
// =====================================================================
__global__ __launch_bounds__(512) __cluster_dims__(8, 1, 1)
void k_lstm(const float* __restrict__ W_ih, const float* __restrict__ b_ih,
            const float* __restrict__ b_hh, const float* __restrict__ W_hh,
            const float* __restrict__ cls_W, const float* __restrict__ cls_b,
            float* __restrict__ out)
{
    __shared__ float hsb[2 * 288];        // [buf][(k>>5)*36 + (k&31)]
    __shared__ float gdm[132];            // gates q = hu_l*4+gate
    __shared__ float iht[Tn * 32 * 4];    // [(t*32+hu_l)*4 + gate]
    __shared__ float embt[Tn * 260];      // emb for this batch, padded rows
    __shared__ float bsm[128];

    const int tid = threadIdx.x;
    uint32_t rank; asm("mov.u32 %0, %%cluster_ctarank;" : "=r"(rank));
    const int b  = blockIdx.x >> 3;       // batch = cluster id
    const int kc = tid & 7;               // k-chunk [32kc, 32kc+32)
    const int jp = tid >> 3;              // 0..63 -> rows {2jp, 2jp+1}
    const int q0 = 2 * jp, q1 = 2 * jp + 1;
    // global gate-row index for local row q: j = gate*256 + rank*32 + hu_l
    const int j0 = (q0 & 3) * Hn + (int)rank * 32 + (q0 >> 2);
    const int j1 = (q1 & 3) * Hn + (int)rank * 32 + (q1 >> 2);

    // --- stage emb rows for this batch: graph g = t*16 + b -------------------
    for (int idx = tid; idx < Tn * Hn; idx += 512) {
        const int t = idx >> 8, k = idx & 255;
        embt[t * 260 + k] = g_emb[(size_t)(t * Bn + b) * Hn + k];
    }
    if (tid < 128) bsm[tid] = b_ih[(tid & 3) * Hn + (int)rank * 32 + (tid >> 2)]
                            + b_hh[(tid & 3) * Hn + (int)rank * 32 + (tid >> 2)];
    for (int i = tid; i < 2 * 288; i += 512) hsb[i] = 0.f;

    unsigned long long wA[16], wB[16];
    // --- phase 1: wA/wB = W_ih rows; compute iht ------------------------------
    {
        const float* r0 = W_ih + (size_t)j0 * Hn + kc * 32;
        const float* r1 = W_ih + (size_t)j1 * Hn + kc * 32;
        #pragma unroll
        for (int i = 0; i < 16; i++) {
            wA[i] = pk2(r0[2 * i], r0[2 * i + 1]);
            wB[i] = pk2(r1[2 * i], r1[2 * i + 1]);
        }
    }
    __syncthreads();
    for (int t = 0; t < Tn; t++) {
        const ulonglong2* ev = (const ulonglong2*)&embt[t * 260 + kc * 32];
        unsigned long long aA = 0, aB = 0;
        #pragma unroll
        for (int i2 = 0; i2 < 8; i2++) {
            const ulonglong2 e2 = ev[i2];
            aA = ffma2(e2.x, wA[2 * i2],     aA);
            aA = ffma2(e2.y, wA[2 * i2 + 1], aA);
            aB = ffma2(e2.x, wB[2 * i2],     aB);
            aB = ffma2(e2.y, wB[2 * i2 + 1], aB);
        }
        float fA = hsum2(aA), fB = hsum2(aB);
        fA += __shfl_xor_sync(0xFFFFFFFFu, fA, 1);
        fA += __shfl_xor_sync(0xFFFFFFFFu, fA, 2);
        fA += __shfl_xor_sync(0xFFFFFFFFu, fA, 4);
        fB += __shfl_xor_sync(0xFFFFFFFFu, fB, 1);
        fB += __shfl_xor_sync(0xFFFFFFFFu, fB, 2);
        fB += __shfl_xor_sync(0xFFFFFFFFu, fB, 4);
        if (kc == 0) {
            iht[(t * 32 + (q0 >> 2)) * 4 + (q0 & 3)] = fA + bsm[q0];
            iht[(t * 32 + (q1 >> 2)) * 4 + (q1 & 3)] = fB + bsm[q1];
        }
    }

    // --- phase 2: wA/wB = W_hh rows -------------------------------------------
    {
        const float* r0 = W_hh + (size_t)j0 * Hn + kc * 32;
        const float* r1 = W_hh + (size_t)j1 * Hn + kc * 32;
        #pragma unroll
        for (int i = 0; i < 16; i++) {
            wA[i] = pk2(r0[2 * i], r0[2 * i + 1]);
            wB[i] = pk2(r1[2 * i], r1[2 * i + 1]);
        }
    }
    __syncthreads();
    CLUSTER_SYNC_();

    float creg = 0.f;   // c for hidden unit rank*32 + tid (threads 0..31)

    for (int t = 0; t < Tn; t++) {
        const ulonglong2* hv = (const ulonglong2*)&hsb[(t & 1) * 288 + kc * 36];
        unsigned long long aA = 0, aB = 0;
        #pragma unroll
        for (int i2 = 0; i2 < 8; i2++) {
            const ulonglong2 h2 = hv[i2];
            aA = ffma2(h2.x, wA[2 * i2],     aA);
            aA = ffma2(h2.y, wA[2 * i2 + 1], aA);
            aB = ffma2(h2.x, wB[2 * i2],     aB);
            aB = ffma2(h2.y, wB[2 * i2 + 1], aB);
        }
        float fA = hsum2(aA), fB = hsum2(aB);
        fA += __shfl_xor_sync(0xFFFFFFFFu, fA, 1);
        fA += __shfl_xor_sync(0xFFFFFFFFu, fA, 2);
        fA += __shfl_xor_sync(0xFFFFFFFFu, fA, 4);
        fB += __shfl_xor_sync(0xFFFFFFFFu, fB, 1);
        fB += __shfl_xor_sync(0xFFFFFFFFu, fB, 2);
        fB += __shfl_xor_sync(0xFFFFFFFFu, fB, 4);
        if (kc == 0) { gdm[q0] = fA; gdm[q1] = fB; }
        __syncthreads();

        if (tid < 32) {
            const int eh = tid;
            const float4 ihv = *(const float4*)&iht[(t * 32 + eh) * 4];
            const float gi = gdm[eh * 4 + 0] + ihv.x;
            const float gf = gdm[eh * 4 + 1] + ihv.y;
            const float gg = gdm[eh * 4 + 2] + ihv.z;
            const float go = gdm[eh * 4 + 3] + ihv.w;
            creg = sigmoidf_(gf) * creg + sigmoidf_(gi) * tanhf(gg);
            const float hn = sigmoidf_(go) * tanhf(creg);
            const uint32_t laddr =
                smem_u32(&hsb[((t + 1) & 1) * 288 + (int)rank * 36 + eh]);
            #pragma unroll
            for (int dr = 0; dr < 8; dr++) {
                uint32_t ra;
                asm("mapa.shared::cluster.u32 %0, %1, %2;" : "=r"(ra) : "r"(laddr), "r"(dr));
                asm volatile("st.shared::cluster.f32 [%0], %1;" :: "r"(ra), "f"(hn) : "memory");
            }
        }
        CLUSTER_SYNC_();
    }

    // final h (after 16 steps) in hsb buf 0 of every CTA; rank 0 classifies
    if (rank == 0 && tid < 32) {
        float p = 0.f;
        #pragma unroll
        for (int i = 0; i < 8; i++)
            p += hsb[i * 36 + tid] * __ldg(&cls_W[i * 32 + tid]);
        #pragma unroll
        for (int o = 16; o; o >>= 1) p += __shfl_xor_sync(0xFFFFFFFFu, p, o);
        if (tid == 0) out[b] = p + cls_b[0];
    }
    CLUSTER_SYNC_();
}

// =====================================================================
extern "C" void kernel_launch(void* const* d_in, const int* in_sizes, int n_in,
                              void* d_out, int out_size)
{
    (void)in_sizes; (void)n_in; (void)out_size;
    const float* x     = (const float*)d_in[0];
    const int*   ei    = (const int*)  d_in[1];
    const float* W1    = (const float*)d_in[2];
    const float* b1    = (const float*)d_in[3];
    const float* Wl    = (const float*)d_in[4];
    const float* Wr    = (const float*)d_in[5];
    const float* sb    = (const float*)d_in[6];
    const float* W2    = (const float*)d_in[7];
    const float* b2    = (const float*)d_in[8];
    const float* W_ih  = (const float*)d_in[9];
    const float* W_hh  = (const float*)d_in[10];
    const float* b_ih  = (const float*)d_in[11];
    const float* b_hh  = (const float*)d_in[12];
    const float* cls_W = (const float*)d_in[13];
    const float* cls_b = (const float*)d_in[14];
    float* out = (float*)d_out;

    const size_t smem1 = 55620 * sizeof(float);  // 222480 B
    cudaFuncSetAttribute(k_embed, cudaFuncAttributeMaxDynamicSharedMemorySize, (int)smem1);

    k_embed<<<NG, NT, smem1>>>(x, ei, W1, b1, Wl, Wr, sb, W2, b2);
    k_lstm <<<128, 512>>>(W_ih, b_ih, b_hh, W_hh, cls_W, cls_b, out);
}